// round 12
// baseline (speedup 1.0000x reference)
#include <cuda_runtime.h>
#include <cuda_fp16.h>
#include <cstdint>
#include <math.h>

// ---------------------------------------------------------------------------
// Problem constants
// ---------------------------------------------------------------------------
#define BQ 8
#define NQ 2048
#define DQ 512
#define MTOT (BQ * NQ)   // 16384

// ---------------------------------------------------------------------------
// Device scratch (no runtime allocation allowed)
// ---------------------------------------------------------------------------
__device__ __half g_x_hi[MTOT * DQ], g_x_lo[MTOT * DQ];
__device__ __half g_w_hi[DQ * DQ],   g_w_lo[DQ * DQ];
__device__ __half g_at_hi[DQ * DQ],  g_at_lo[DQ * DQ];     // attn^T
__device__ __half g_h_hi[MTOT * DQ],  g_h_lo[MTOT * DQ];
__device__ __half g_ht_hi[MTOT * DQ];                      // per-batch H^T (hi only)
__device__ __half g_ha_hi[MTOT * DQ], g_ha_lo[MTOT * DQ];
__device__ __half g_p[(size_t)BQ * NQ * NQ];               // softmax weights, fp16
__device__ float g_s[(size_t)BQ * NQ * NQ];

// ---------------------------------------------------------------------------
// Low-level helpers (base compute_103 features only)
// ---------------------------------------------------------------------------
__device__ __forceinline__ uint32_t smem_u32(const void* p) {
    uint32_t a;
    asm("{ .reg .u64 t; cvta.to.shared.u64 t, %1; cvt.u32.u64 %0, t; }" : "=r"(a) : "l"(p));
    return a;
}

#define CP16(dst, src) \
    asm volatile("cp.async.cg.shared.global [%0], [%1], 16;\n" :: "r"(dst), "l"(src) : "memory")
#define CP_COMMIT() asm volatile("cp.async.commit_group;\n" ::: "memory")
#define CP_WAIT1()  asm volatile("cp.async.wait_group 1;\n" ::: "memory")

__device__ __forceinline__ void ldsm4(uint32_t* r, uint32_t addr) {
    asm volatile("ldmatrix.sync.aligned.m8n8.x4.shared.b16 {%0,%1,%2,%3}, [%4];\n"
                 : "=r"(r[0]), "=r"(r[1]), "=r"(r[2]), "=r"(r[3]) : "r"(addr));
}

__device__ __forceinline__ void mma16816(float* c, const uint32_t* a, const uint32_t* b) {
    asm volatile(
        "mma.sync.aligned.m16n8k16.row.col.f32.f16.f16.f32 "
        "{%0,%1,%2,%3}, {%4,%5,%6,%7}, {%8,%9}, {%0,%1,%2,%3};\n"
        : "+f"(c[0]), "+f"(c[1]), "+f"(c[2]), "+f"(c[3])
        : "r"(a[0]), "r"(a[1]), "r"(a[2]), "r"(a[3]), "r"(b[0]), "r"(b[1]));
}

// ---------------------------------------------------------------------------
// Unified HMMA GEMM: C[m,n] = sum_k A[m,k] * B[n,k] via fp16 split 3-pass
// (all fp32 accumulation -- R10 numerics, bit-identical results).
//
// MODES 1-3 (split): CTA tile 256x128, 256 threads = 8 warps (4 M x 2 N),
//   warp tile 64x64. Two M-warps share each B tile -> per-SMSP LDGSTS issue
//   drops from 256 to 192 cyc/stage; MIO ceiling rises 75% -> 86%.
// MODE 4 (single fp16): CTA tile 128x128, 128 threads, 2 CTAs/SM (balanced).
//
// MODE 1: out = C + bias -> h hi/lo + fused hT_hi   (M=16384, N=512, K=512)
// MODE 2: out = C        -> ha hi/lo                 (M=16384, N=512, K=512)
// MODE 3: out = mask(C)  -> scores fp32   (per batch, M=N=2048, K=512)
// MODE 4: out = elu(C)   -> fp32          (per batch, M=2048, N=512, K=2048)
// SMEM swizzles: 128B rows phys = row*128 + (off ^ ((row&7)<<4));
//                64B rows phys = row*64 + (off ^ ((row&3)<<4)).
// ---------------------------------------------------------------------------
template <int MODE>
__global__ __launch_bounds__((MODE == 4) ? 128 : 256, (MODE == 4) ? 2 : 1)
void k_mma(
    const __half* __restrict__ Ahi, const __half* __restrict__ Alo,
    const __half* __restrict__ Bhi, const __half* __restrict__ Blo,
    const float* __restrict__ bias, const int* __restrict__ adj,
    float* __restrict__ outf,
    __half* __restrict__ out_hi, __half* __restrict__ out_lo,
    __half* __restrict__ out_t)
{
    constexpr bool SPL  = (MODE != 4);
    constexpr int KDIM = (MODE == 4) ? 2048 : 512;
    constexpr int LDA  = (MODE == 4) ? 2048 : 512;
    constexpr int LDB  = (MODE == 4) ? 2048 : 512;
    constexpr int NST  = KDIM / 32;
    constexpr int TM   = SPL ? 256 : 128;        // CTA M tile
    constexpr int ASB  = SPL ? 32768 : 8192;     // A tile bytes
    constexpr int BSB  = SPL ? 16384 : 8192;     // B tile bytes
    constexpr int STG  = ASB + BSB;              // stage bytes

    extern __shared__ char smem[];
    const uint32_t sbase = smem_u32(smem);
    const int tid = threadIdx.x;
    const int lane = tid & 31, wid = tid >> 5;
    const int warp_m = SPL ? (wid & 3) : (wid & 1);   // M warps: 4 (SPL) / 2
    const int warp_n = SPL ? (wid >> 2) : (wid >> 1); // N warps: 2

    const int bn = blockIdx.x * 128, bm = blockIdx.y * TM, z = blockIdx.z;
    size_t aoff = 0, boff = 0;
    if (MODE == 3) { aoff = (size_t)z * NQ * DQ; boff = (size_t)z * NQ * DQ; }
    if (MODE == 4) { aoff = (size_t)z * NQ * NQ; boff = (size_t)z * DQ * NQ; }

    const char* A0h = (const char*)(Ahi + aoff + (size_t)bm * LDA);
    const char* A0l = (const char*)(Alo + aoff + (size_t)bm * LDA);
    const char* B0h = (const char*)(Bhi + boff + (size_t)bn * LDB);
    const char* B0l = (const char*)(Blo + boff + (size_t)bn * LDB);

    auto issue_stage = [&](uint32_t sd, int kb) {
        if (SPL) {
            // 256 threads: A 256 rows x 128B [hi|lo], B 128 rows x 128B [hi|lo]
            const uint32_t row0 = tid >> 3;           // 0..31
            const uint32_t c = tid & 7;
            const uint32_t off = c * 16;
            const char* srcA = (c < 4) ? A0h : A0l;
            const char* srcB = (c < 4) ? B0h : B0l;
            const int cb = (c & 3) * 16;
#pragma unroll
            for (int blk = 0; blk < 8; ++blk) {       // A: 256 rows
                const uint32_t row = row0 + blk * 32;
                const uint32_t sw = row * 128 + (off ^ ((row & 7) << 4));
                CP16(sd + sw, srcA + (size_t)row * (LDA * 2) + kb + cb);
            }
#pragma unroll
            for (int blk = 0; blk < 4; ++blk) {       // B: 128 rows
                const uint32_t row = row0 + blk * 32;
                const uint32_t sw = row * 128 + (off ^ ((row & 7) << 4));
                CP16(sd + ASB + sw, srcB + (size_t)row * (LDB * 2) + kb + cb);
            }
        } else {
            // 128 threads: A,B each 128 rows x 64B [hi only]
            const uint32_t row0 = tid >> 2;
            const uint32_t c = tid & 3;
            const uint32_t off = c * 16;
#pragma unroll
            for (int blk = 0; blk < 4; ++blk) {
                const uint32_t row = row0 + blk * 32;
                const uint32_t sw = row * 64 + (off ^ ((row & 3) << 4));
                CP16(sd + sw,       A0h + (size_t)row * (LDA * 2) + kb + c * 16);
                CP16(sd + ASB + sw, B0h + (size_t)row * (LDB * 2) + kb + c * 16);
            }
        }
    };

    // per-lane ldmatrix row bases (A: 4 m16 tiles, B: 4 n16 groups)
    uint32_t a_rt[4], a_sw[4];
#pragma unroll
    for (int mi = 0; mi < 4; ++mi) {
        const uint32_t r = warp_m * 64 + mi * 16 + (lane & 15);
        if (SPL) { a_rt[mi] = r * 128; a_sw[mi] = (r & 7) << 4; }
        else     { a_rt[mi] = r * 64;  a_sw[mi] = (r & 3) << 4; }
    }
    uint32_t b_rt[4], b_sw[4];
    {
        const uint32_t brow = (lane & 7) + ((lane >> 4) & 1) * 8;
#pragma unroll
        for (int jp = 0; jp < 4; ++jp) {
            const uint32_t r = warp_n * 64 + jp * 16 + brow;
            if (SPL) { b_rt[jp] = r * 128; b_sw[jp] = (r & 7) << 4; }
            else     { b_rt[jp] = r * 64;  b_sw[jp] = (r & 3) << 4; }
        }
    }
    const uint32_t a_koff = (lane >> 4) * 16;        // 0 or 16
    const uint32_t b_koff = ((lane >> 3) & 1) * 16;  // 0 or 16

    float acc[4][8][4];
#pragma unroll
    for (int i = 0; i < 4; ++i)
#pragma unroll
        for (int j = 0; j < 8; ++j)
#pragma unroll
            for (int k = 0; k < 4; ++k) acc[i][j][k] = 0.f;

    // prologue: stages 0, 1
    issue_stage(sbase, 0);
    CP_COMMIT();
    issue_stage(sbase + STG, 64);
    CP_COMMIT();

    int buf = 0, nbuf = 2;
    for (int i = 0; i < NST; ++i) {
        CP_WAIT1();
        __syncthreads();
        if (i + 2 < NST)
            issue_stage(sbase + nbuf * STG, (i + 2) * 64);
        CP_COMMIT();   // empty group when not issuing keeps wait_group 1 exact

        const uint32_t sa = sbase + buf * STG;
        const uint32_t sb = sa + ASB;
#pragma unroll
        for (int ks = 0; ks < 2; ++ks) {
            const uint32_t ko = ks * 32;
            uint32_t ah[4][4], al[4][4];
#pragma unroll
            for (int mi = 0; mi < 4; ++mi) {
                ldsm4(ah[mi], sa + a_rt[mi] + ((ko + a_koff) ^ a_sw[mi]));
                if (SPL)
                    ldsm4(al[mi], sa + a_rt[mi] + ((ko + a_koff + 64) ^ a_sw[mi]));
            }
#pragma unroll
            for (int jp = 0; jp < 4; ++jp) {
                uint32_t bh[4], bl[4];
                ldsm4(bh, sb + b_rt[jp] + ((ko + b_koff) ^ b_sw[jp]));
                if (SPL)
                    ldsm4(bl, sb + b_rt[jp] + ((ko + b_koff + 64) ^ b_sw[jp]));
#pragma unroll
                for (int mi = 0; mi < 4; ++mi) {
                    mma16816(acc[mi][2*jp],   ah[mi], bh);
                    if (SPL) {
                        mma16816(acc[mi][2*jp], ah[mi], bl);
                        mma16816(acc[mi][2*jp], al[mi], bh);
                    }
                    mma16816(acc[mi][2*jp+1], ah[mi], bh + 2);
                    if (SPL) {
                        mma16816(acc[mi][2*jp+1], ah[mi], bl + 2);
                        mma16816(acc[mi][2*jp+1], al[mi], bh + 2);
                    }
                }
            }
        }
        buf = (buf == 2) ? 0 : buf + 1;
        nbuf = (nbuf == 2) ? 0 : nbuf + 1;
    }

    // -----------------------------------------------------------------------
    // Epilogue
    // -----------------------------------------------------------------------
    const int rbase = bm + warp_m * 64 + (lane >> 2);
    const int cbase = bn + warp_n * 64 + (lane & 3) * 2;

    // For MODE 1: stage hi values into smem for the fused transpose.
    // [128 d][264 n] fp16 = 67.6KB, placed in stage-1/2 area (reused).
    __half* st = (__half*)(smem + STG);
    if (MODE == 1) __syncthreads();       // all MMA reads of stage smem done

#pragma unroll
    for (int mi = 0; mi < 4; ++mi) {
#pragma unroll
        for (int j = 0; j < 8; ++j) {
            const int gc = cbase + j * 8;
#pragma unroll
            for (int half = 0; half < 2; ++half) {
                const int gr = rbase + mi * 16 + half * 8;
                float v0 = acc[mi][j][half * 2 + 0];
                float v1 = acc[mi][j][half * 2 + 1];
                if (MODE == 1) {
                    const float2 bv = *(const float2*)(bias + gc);
                    v0 += bv.x; v1 += bv.y;
                }
                if (MODE == 1 || MODE == 2) {
                    const __half h0 = __float2half(v0);
                    const __half h1 = __float2half(v1);
                    __half2 hp; hp.x = h0; hp.y = h1;
                    __half2 lp;
                    lp.x = __float2half(v0 - __half2float(h0));
                    lp.y = __float2half(v1 - __half2float(h1));
                    *(__half2*)(out_hi + (size_t)gr * DQ + gc) = hp;
                    *(__half2*)(out_lo + (size_t)gr * DQ + gc) = lp;
                    if (MODE == 1) {
                        st[(gc - bn)     * 264 + (gr - bm)] = h0;
                        st[(gc + 1 - bn) * 264 + (gr - bm)] = h1;
                    }
                } else if (MODE == 3) {
                    const size_t o = (size_t)z * NQ * NQ + (size_t)gr * NQ + gc;
                    const int2 ad = *(const int2*)(adj + o);
                    float2 ov;
                    ov.x = ad.x ? v0 : -1e30f;
                    ov.y = ad.y ? v1 : -1e30f;
                    *(float2*)(outf + o) = ov;
                } else {
                    const size_t o = (size_t)z * NQ * DQ + (size_t)gr * DQ + gc;
                    float2 ov;
                    ov.x = (v0 > 0.f) ? v0 : expm1f(v0);
                    ov.y = (v1 > 0.f) ? v1 : expm1f(v1);
                    *(float2*)(outf + o) = ov;
                }
            }
        }
    }

    if (MODE == 1) {
        __syncthreads();
        // coalesced transposed write: 256 threads, 2 per d-row
        const int b = bm >> 11, n0 = bm & 2047;     // bm multiple of 256
        const int dr = tid >> 1;                    // 0..127
        const int nh = (tid & 1) * 128;             // n half within 256
        const __half* src = st + dr * 264 + nh;
        __half* dst = out_t + ((size_t)(b * DQ + bn + dr)) * NQ + n0 + nh;
#pragma unroll
        for (int k2 = 0; k2 < 16; ++k2)
            *(float4*)(dst + k2 * 8) = *(const float4*)(src + k2 * 8);
    }
}

#define SMEM_G3P (3 * 49152)             // MODE 1/2/3: 147456
#define SMEM_G4  (3 * 16384)             // MODE 4: 49152

// ---------------------------------------------------------------------------
// fp32 -> fp16 hi/lo split (elementwise)
// ---------------------------------------------------------------------------
__global__ __launch_bounds__(256) void k_split(
    const float* __restrict__ in, __half* __restrict__ hi,
    __half* __restrict__ lo, int n)
{
    for (int i = blockIdx.x * 256 + threadIdx.x; i < n; i += gridDim.x * 256) {
        const float v = in[i];
        const __half h = __float2half(v);
        hi[i] = h;
        lo[i] = __float2half(v - __half2float(h));
    }
}

// attn [K,N] fp32 -> attn^T [N,K] fp16 hi/lo
__global__ __launch_bounds__(256) void k_split_T(
    const float* __restrict__ in, __half* __restrict__ hi,
    __half* __restrict__ lo)
{
    for (int i = blockIdx.x * 256 + threadIdx.x; i < DQ * DQ; i += gridDim.x * 256) {
        const int n = i / DQ, k = i % DQ;
        const float v = in[(size_t)k * DQ + n];
        const __half h = __float2half(v);
        hi[i] = h;
        lo[i] = __float2half(v - __half2float(h));
    }
}

// ---------------------------------------------------------------------------
// Row softmax over scores -> P fp16. 512 threads, 4 elems/thread, shfl+smem.
// ---------------------------------------------------------------------------
__global__ __launch_bounds__(512) void k_softmax(
    const float* __restrict__ S, __half* __restrict__ P)
{
    __shared__ float red[16];
    const size_t base = (size_t)blockIdx.x * NQ;
    const int tid = threadIdx.x;
    const int lane = tid & 31, wid = tid >> 5;

    float4 v = *(const float4*)(S + base + tid * 4);

    float m = fmaxf(fmaxf(v.x, v.y), fmaxf(v.z, v.w));
#pragma unroll
    for (int o = 16; o > 0; o >>= 1)
        m = fmaxf(m, __shfl_xor_sync(0xffffffff, m, o));
    if (lane == 0) red[wid] = m;
    __syncthreads();
    if (wid == 0) {
        float t = red[lane & 15];
#pragma unroll
        for (int o = 8; o > 0; o >>= 1)
            t = fmaxf(t, __shfl_xor_sync(0xffffffff, t, o));
        if (lane == 0) red[0] = t;
    }
    __syncthreads();
    m = red[0];

    v.x = expf(v.x - m); v.y = expf(v.y - m);
    v.z = expf(v.z - m); v.w = expf(v.w - m);
    float s = v.x + v.y + v.z + v.w;
#pragma unroll
    for (int o = 16; o > 0; o >>= 1)
        s += __shfl_xor_sync(0xffffffff, s, o);
    __syncthreads();
    if (lane == 0) red[wid] = s;
    __syncthreads();
    if (wid == 0) {
        float t = red[lane & 15];
#pragma unroll
        for (int o = 8; o > 0; o >>= 1)
            t += __shfl_xor_sync(0xffffffff, t, o);
        if (lane == 0) red[0] = t;
    }
    __syncthreads();
    const float inv = 1.f / red[0];

    __half2 o0, o1;
    o0.x = __float2half(v.x * inv); o0.y = __float2half(v.y * inv);
    o1.x = __float2half(v.z * inv); o1.y = __float2half(v.w * inv);
    __half2* dst = (__half2*)(P + base + tid * 4);
    dst[0] = o0; dst[1] = o1;
}

// ---------------------------------------------------------------------------
// Launch
// ---------------------------------------------------------------------------
extern "C" void kernel_launch(void* const* d_in, const int* in_sizes, int n_in,
                              void* d_out, int out_size)
{
    const float* x    = (const float*)d_in[0];
    const int*   adj  = (const int*)  d_in[1];
    const float* W    = (const float*)d_in[2];
    const float* bias = (const float*)d_in[3];
    const float* attn = (const float*)d_in[4];
    float* out = (float*)d_out;

    __half *x_hi, *x_lo, *w_hi, *w_lo, *at_hi, *at_lo;
    __half *h_hi, *h_lo, *ht_hi, *ha_hi, *ha_lo, *p;
    float* s;
    cudaGetSymbolAddress((void**)&x_hi,  g_x_hi);  cudaGetSymbolAddress((void**)&x_lo,  g_x_lo);
    cudaGetSymbolAddress((void**)&w_hi,  g_w_hi);  cudaGetSymbolAddress((void**)&w_lo,  g_w_lo);
    cudaGetSymbolAddress((void**)&at_hi, g_at_hi); cudaGetSymbolAddress((void**)&at_lo, g_at_lo);
    cudaGetSymbolAddress((void**)&h_hi,  g_h_hi);  cudaGetSymbolAddress((void**)&h_lo,  g_h_lo);
    cudaGetSymbolAddress((void**)&ht_hi, g_ht_hi);
    cudaGetSymbolAddress((void**)&ha_hi, g_ha_hi); cudaGetSymbolAddress((void**)&ha_lo, g_ha_lo);
    cudaGetSymbolAddress((void**)&p,     g_p);
    cudaGetSymbolAddress((void**)&s,     g_s);

    cudaFuncSetAttribute(k_mma<1>, cudaFuncAttributeMaxDynamicSharedMemorySize, SMEM_G3P);
    cudaFuncSetAttribute(k_mma<2>, cudaFuncAttributeMaxDynamicSharedMemorySize, SMEM_G3P);
    cudaFuncSetAttribute(k_mma<3>, cudaFuncAttributeMaxDynamicSharedMemorySize, SMEM_G3P);
    cudaFuncSetAttribute(k_mma<4>, cudaFuncAttributeMaxDynamicSharedMemorySize, SMEM_G4);

    // Input splits
    k_split<<<4096, 256>>>(x, x_hi, x_lo, MTOT * DQ);
    k_split<<<512, 256>>>(W, w_hi, w_lo, DQ * DQ);
    k_split_T<<<512, 256>>>(attn, at_hi, at_lo);

    // h = x @ W^T + b  (3-pass, 256x128 tile), hT_hi produced in epilogue
    k_mma<1><<<dim3(DQ / 128, MTOT / 256, 1), 256, SMEM_G3P>>>(
        x_hi, x_lo, w_hi, w_lo, bias, nullptr, nullptr, h_hi, h_lo, ht_hi);

    // ha = h @ attn  (3-pass, 256x128 tile)
    k_mma<2><<<dim3(DQ / 128, MTOT / 256, 1), 256, SMEM_G3P>>>(
        h_hi, h_lo, at_hi, at_lo, nullptr, nullptr, nullptr, ha_hi, ha_lo, nullptr);

    // scores = ha @ h^T (per batch), adjacency-masked  (3-pass, 256x128 tile)
    k_mma<3><<<dim3(NQ / 128, NQ / 256, BQ), 256, SMEM_G3P>>>(
        ha_hi, ha_lo, h_hi, h_lo, nullptr, adj, s, nullptr, nullptr, nullptr);

    // softmax rows -> P fp16
    k_softmax<<<BQ * NQ, 512>>>(s, p);

    // out = elu(P @ h) per batch  (1-pass, 128x128 tile)
    k_mma<4><<<dim3(DQ / 128, NQ / 128, BQ), 128, SMEM_G4>>>(
        p, p, ht_hi, ht_hi, nullptr, nullptr, out, nullptr, nullptr, nullptr);
}

// round 13
// speedup vs baseline: 1.1414x; 1.1414x over previous
#include <cuda_runtime.h>
#include <cuda_fp16.h>
#include <cstdint>
#include <math.h>

// ---------------------------------------------------------------------------
// Problem constants
// ---------------------------------------------------------------------------
#define BQ 8
#define NQ 2048
#define DQ 512
#define MTOT (BQ * NQ)   // 16384

// ---------------------------------------------------------------------------
// Device scratch (no runtime allocation allowed)
// ---------------------------------------------------------------------------
__device__ __half g_x_hi[MTOT * DQ], g_x_lo[MTOT * DQ];
__device__ __half g_w_hi[DQ * DQ],   g_w_lo[DQ * DQ];
__device__ __half g_at_hi[DQ * DQ],  g_at_lo[DQ * DQ];     // attn^T
__device__ __half g_h_hi[MTOT * DQ],  g_h_lo[MTOT * DQ];
__device__ __half g_ht_hi[MTOT * DQ];                      // per-batch H^T (hi only)
__device__ __half g_ha_hi[MTOT * DQ], g_ha_lo[MTOT * DQ];
__device__ __half g_p[(size_t)BQ * NQ * NQ];               // softmax weights, fp16
__device__ float g_s[(size_t)BQ * NQ * NQ];

// ---------------------------------------------------------------------------
// Low-level helpers (base compute_103 features only)
// ---------------------------------------------------------------------------
__device__ __forceinline__ uint32_t smem_u32(const void* p) {
    uint32_t a;
    asm("{ .reg .u64 t; cvta.to.shared.u64 t, %1; cvt.u32.u64 %0, t; }" : "=r"(a) : "l"(p));
    return a;
}

#define CP16(dst, src) \
    asm volatile("cp.async.cg.shared.global [%0], [%1], 16;\n" :: "r"(dst), "l"(src) : "memory")
#define CP_COMMIT() asm volatile("cp.async.commit_group;\n" ::: "memory")
#define CP_WAIT1()  asm volatile("cp.async.wait_group 1;\n" ::: "memory")
#define CP_WAIT2()  asm volatile("cp.async.wait_group 2;\n" ::: "memory")

__device__ __forceinline__ void ldsm4(uint32_t* r, uint32_t addr) {
    asm volatile("ldmatrix.sync.aligned.m8n8.x4.shared.b16 {%0,%1,%2,%3}, [%4];\n"
                 : "=r"(r[0]), "=r"(r[1]), "=r"(r[2]), "=r"(r[3]) : "r"(addr));
}

__device__ __forceinline__ void mma16816(float* c, const uint32_t* a, const uint32_t* b) {
    asm volatile(
        "mma.sync.aligned.m16n8k16.row.col.f32.f16.f16.f32 "
        "{%0,%1,%2,%3}, {%4,%5,%6,%7}, {%8,%9}, {%0,%1,%2,%3};\n"
        : "+f"(c[0]), "+f"(c[1]), "+f"(c[2]), "+f"(c[3])
        : "r"(a[0]), "r"(a[1]), "r"(a[2]), "r"(a[3]), "r"(b[0]), "r"(b[1]));
}

// ---------------------------------------------------------------------------
// Unified HMMA GEMM: C[m,n] = sum_k A[m,k] * B[n,k] via fp16 split
// R10 champion config: CTA tile 128x128, 128 threads = 4 warps (2M x 2N),
// warp 64x64, fp32 accumulation, pass-major inner loop.
// MODES 1-3: 3-pass (hh + hl + lh), 3-stage pipeline (32KB stages).
// MODE 4:    1-pass (P fp16 x hT_hi fp16), 4-stage pipeline (16KB stages).
// MODE 1: out = C + bias -> h hi/lo + fused hT_hi   (M=16384,N=512,K=512)
// MODE 2: out = C        -> ha hi/lo                 (M=16384,N=512,K=512)
// MODE 3: out = mask(C)  -> scores fp32   (per batch, M=N=2048, K=512)
// MODE 4: out = elu(C)   -> fp32          (per batch, M=2048, N=512, K=2048)
// SMEM swizzles: 128B rows phys = row*128 + (off ^ ((row&7)<<4));
//                64B rows phys = row*64 + (off ^ ((row&3)<<4)).
// ---------------------------------------------------------------------------
template <int MODE>
__global__ __launch_bounds__(128, 2) void k_mma(
    const __half* __restrict__ Ahi, const __half* __restrict__ Alo,
    const __half* __restrict__ Bhi, const __half* __restrict__ Blo,
    const float* __restrict__ bias, const int* __restrict__ adj,
    float* __restrict__ outf,
    __half* __restrict__ out_hi, __half* __restrict__ out_lo,
    __half* __restrict__ out_t)
{
    constexpr bool SPL  = (MODE != 4);         // split (hi/lo) operands?
    constexpr int KDIM = (MODE == 4) ? 2048 : 512;
    constexpr int LDA  = (MODE == 4) ? 2048 : 512;
    constexpr int LDB  = (MODE == 4) ? 2048 : 512;
    constexpr int NST  = KDIM / 32;
    constexpr int ASB  = SPL ? 16384 : 8192;   // A tile bytes
    constexpr int BSB  = SPL ? 16384 : 8192;   // B tile bytes
    constexpr int STG  = ASB + BSB;            // stage bytes
    constexpr int NSTG = SPL ? 3 : 4;          // pipeline depth

    extern __shared__ char smem[];
    const uint32_t sbase = smem_u32(smem);
    const int tid = threadIdx.x;
    const int lane = tid & 31, wid = tid >> 5;
    const int warp_m = wid & 1;        // 2 warps along M (64 rows each)
    const int warp_n = wid >> 1;       // 2 warps along N (64 cols each)

    const int bn = blockIdx.x * 128, bm = blockIdx.y * 128, z = blockIdx.z;
    size_t aoff = 0, boff = 0;
    if (MODE == 3) { aoff = (size_t)z * NQ * DQ; boff = (size_t)z * NQ * DQ; }
    if (MODE == 4) { aoff = (size_t)z * NQ * NQ; boff = (size_t)z * DQ * NQ; }

    const char* A0h = (const char*)(Ahi + aoff + (size_t)bm * LDA);
    const char* A0l = (const char*)(Alo + aoff + (size_t)bm * LDA);
    const char* B0h = (const char*)(Bhi + boff + (size_t)bn * LDB);
    const char* B0l = (const char*)(Blo + boff + (size_t)bn * LDB);

    auto issue_stage = [&](uint32_t sd, int kb) {
        if (SPL) {
            const uint32_t row0 = tid >> 3;
            const uint32_t c = tid & 7;
            const uint32_t off = c * 16;
            const char* srcA = (c < 4) ? A0h : A0l;
            const char* srcB = (c < 4) ? B0h : B0l;
            const int cb = (c & 3) * 16;
#pragma unroll
            for (int blk = 0; blk < 8; ++blk) {
                const uint32_t row = row0 + blk * 16;
                const uint32_t sw = row * 128 + (off ^ ((row & 7) << 4));
                CP16(sd + sw,       srcA + (size_t)row * (LDA * 2) + kb + cb);
                CP16(sd + ASB + sw, srcB + (size_t)row * (LDB * 2) + kb + cb);
            }
        } else {
            const uint32_t row0 = tid >> 2;
            const uint32_t c = tid & 3;
            const uint32_t off = c * 16;
#pragma unroll
            for (int blk = 0; blk < 4; ++blk) {
                const uint32_t row = row0 + blk * 32;
                const uint32_t sw = row * 64 + (off ^ ((row & 3) << 4));
                CP16(sd + sw,       A0h + (size_t)row * (LDA * 2) + kb + c * 16);
                CP16(sd + ASB + sw, B0h + (size_t)row * (LDB * 2) + kb + c * 16);
            }
        }
    };

    // per-lane ldmatrix row bases (A: 4 m16 tiles, B: 4 n16 groups)
    uint32_t a_rt[4], a_sw[4];
#pragma unroll
    for (int mi = 0; mi < 4; ++mi) {
        const uint32_t r = warp_m * 64 + mi * 16 + (lane & 15);
        if (SPL) { a_rt[mi] = r * 128; a_sw[mi] = (r & 7) << 4; }
        else     { a_rt[mi] = r * 64;  a_sw[mi] = (r & 3) << 4; }
    }
    uint32_t b_rt[4], b_sw[4];
    {
        const uint32_t brow = (lane & 7) + ((lane >> 4) & 1) * 8;
#pragma unroll
        for (int jp = 0; jp < 4; ++jp) {
            const uint32_t r = warp_n * 64 + jp * 16 + brow;
            if (SPL) { b_rt[jp] = r * 128; b_sw[jp] = (r & 7) << 4; }
            else     { b_rt[jp] = r * 64;  b_sw[jp] = (r & 3) << 4; }
        }
    }
    const uint32_t a_koff = (lane >> 4) * 16;        // 0 or 16
    const uint32_t b_koff = ((lane >> 3) & 1) * 16;  // 0 or 16

    float acc[4][8][4];
#pragma unroll
    for (int i = 0; i < 4; ++i)
#pragma unroll
        for (int j = 0; j < 8; ++j)
#pragma unroll
            for (int k = 0; k < 4; ++k) acc[i][j][k] = 0.f;

    // prologue: stages 0 .. NSTG-2
#pragma unroll
    for (int sgi = 0; sgi < NSTG - 1; ++sgi) {
        issue_stage(sbase + sgi * STG, sgi * 64);
        CP_COMMIT();
    }

    int buf = 0, nbuf = NSTG - 1;
    for (int i = 0; i < NST; ++i) {
        if (SPL) { CP_WAIT1(); } else { CP_WAIT2(); }
        __syncthreads();
        if (i + NSTG - 1 < NST)
            issue_stage(sbase + nbuf * STG, (i + NSTG - 1) * 64);
        CP_COMMIT();   // empty group when not issuing keeps wait accounting exact

        const uint32_t sa = sbase + buf * STG;
        const uint32_t sb = sa + ASB;
#pragma unroll
        for (int ks = 0; ks < 2; ++ks) {
            const uint32_t ko = ks * 32;
            uint32_t ah[4][4], al[4][4], bh[4][4], bl[4][4];
#pragma unroll
            for (int mi = 0; mi < 4; ++mi) {
                ldsm4(ah[mi], sa + a_rt[mi] + ((ko + a_koff) ^ a_sw[mi]));
                if (SPL)
                    ldsm4(al[mi], sa + a_rt[mi] + ((ko + a_koff + 64) ^ a_sw[mi]));
            }
#pragma unroll
            for (int jp = 0; jp < 4; ++jp) {
                ldsm4(bh[jp], sb + b_rt[jp] + ((ko + b_koff) ^ b_sw[jp]));
                if (SPL)
                    ldsm4(bl[jp], sb + b_rt[jp] + ((ko + b_koff + 64) ^ b_sw[jp]));
            }
            // pass 1: hi*hi (16 independent accumulators back-to-back)
#pragma unroll
            for (int mi = 0; mi < 4; ++mi)
#pragma unroll
                for (int jp = 0; jp < 4; ++jp) {
                    mma16816(acc[mi][2*jp],   ah[mi], bh[jp]);
                    mma16816(acc[mi][2*jp+1], ah[mi], bh[jp] + 2);
                }
            if (SPL) {
                // pass 2: hi*lo
#pragma unroll
                for (int mi = 0; mi < 4; ++mi)
#pragma unroll
                    for (int jp = 0; jp < 4; ++jp) {
                        mma16816(acc[mi][2*jp],   ah[mi], bl[jp]);
                        mma16816(acc[mi][2*jp+1], ah[mi], bl[jp] + 2);
                    }
                // pass 3: lo*hi
#pragma unroll
                for (int mi = 0; mi < 4; ++mi)
#pragma unroll
                    for (int jp = 0; jp < 4; ++jp) {
                        mma16816(acc[mi][2*jp],   al[mi], bh[jp]);
                        mma16816(acc[mi][2*jp+1], al[mi], bh[jp] + 2);
                    }
            }
        }
        buf = (buf == NSTG - 1) ? 0 : buf + 1;
        nbuf = (nbuf == NSTG - 1) ? 0 : nbuf + 1;
    }

    // -----------------------------------------------------------------------
    // Epilogue
    // -----------------------------------------------------------------------
    const int rbase = bm + warp_m * 64 + (lane >> 2);
    const int cbase = bn + warp_n * 64 + (lane & 3) * 2;

    // For MODE 1: stage hi values into smem for the fused transpose.
    __half* st = (__half*)(smem + STG);   // [128 d][136 n] fp16; stages 1,2 stale
    if (MODE == 1) __syncthreads();       // all MMA reads of stage smem done

#pragma unroll
    for (int mi = 0; mi < 4; ++mi) {
#pragma unroll
        for (int j = 0; j < 8; ++j) {
            const int gc = cbase + j * 8;
#pragma unroll
            for (int half = 0; half < 2; ++half) {
                const int gr = rbase + mi * 16 + half * 8;
                float v0 = acc[mi][j][half * 2 + 0];
                float v1 = acc[mi][j][half * 2 + 1];
                if (MODE == 1) {
                    const float2 bv = *(const float2*)(bias + gc);
                    v0 += bv.x; v1 += bv.y;
                }
                if (MODE == 1 || MODE == 2) {
                    const __half h0 = __float2half(v0);
                    const __half h1 = __float2half(v1);
                    __half2 hp; hp.x = h0; hp.y = h1;
                    __half2 lp;
                    lp.x = __float2half(v0 - __half2float(h0));
                    lp.y = __float2half(v1 - __half2float(h1));
                    *(__half2*)(out_hi + (size_t)gr * DQ + gc) = hp;
                    *(__half2*)(out_lo + (size_t)gr * DQ + gc) = lp;
                    if (MODE == 1) {
                        st[(gc - bn)     * 136 + (gr - bm)] = h0;
                        st[(gc + 1 - bn) * 136 + (gr - bm)] = h1;
                    }
                } else if (MODE == 3) {
                    const size_t o = (size_t)z * NQ * NQ + (size_t)gr * NQ + gc;
                    const int2 ad = *(const int2*)(adj + o);
                    float2 ov;
                    ov.x = ad.x ? v0 : -1e30f;
                    ov.y = ad.y ? v1 : -1e30f;
                    *(float2*)(outf + o) = ov;
                } else {
                    const size_t o = (size_t)z * NQ * DQ + (size_t)gr * DQ + gc;
                    float2 ov;
                    ov.x = (v0 > 0.f) ? v0 : expm1f(v0);
                    ov.y = (v1 > 0.f) ? v1 : expm1f(v1);
                    *(float2*)(outf + o) = ov;
                }
            }
        }
    }

    if (MODE == 1) {
        __syncthreads();
        // coalesced transposed write: thread tid owns d-row (bn + tid)
        const int b = bm >> 11, n0 = bm & 2047;
        const __half* src = st + tid * 136;
        __half* dst = out_t + ((size_t)(b * DQ + bn + tid)) * NQ + n0;
#pragma unroll
        for (int k2 = 0; k2 < 16; ++k2)
            *(float4*)(dst + k2 * 8) = *(const float4*)(src + k2 * 8);
    }
}

#define SMEM_G3P (3 * 32768)             // MODE 1/2/3: 98304
#define SMEM_G4  (4 * 16384)             // MODE 4: 65536

// ---------------------------------------------------------------------------
// fp32 -> fp16 hi/lo split, vectorized (x input: n4 float4 elements)
// ---------------------------------------------------------------------------
__global__ __launch_bounds__(256) void k_split4(
    const float4* __restrict__ in, __half2* __restrict__ hi,
    __half2* __restrict__ lo, int n4)
{
    for (int i = blockIdx.x * 256 + threadIdx.x; i < n4; i += gridDim.x * 256) {
        const float4 v = in[i];
        const __half2 h0 = __floats2half2_rn(v.x, v.y);
        const __half2 h1 = __floats2half2_rn(v.z, v.w);
        const float2 f0 = __half22float2(h0);
        const float2 f1 = __half22float2(h1);
        hi[2*i]   = h0;
        hi[2*i+1] = h1;
        lo[2*i]   = __floats2half2_rn(v.x - f0.x, v.y - f0.y);
        lo[2*i+1] = __floats2half2_rn(v.z - f1.x, v.w - f1.y);
    }
}

// Merged small splits: W (elementwise) and attn (transposed), both DQxDQ.
__global__ __launch_bounds__(256) void k_split_small(
    const float* __restrict__ W, __half* __restrict__ whi, __half* __restrict__ wlo,
    const float* __restrict__ attn, __half* __restrict__ ahi, __half* __restrict__ alo)
{
    for (int i = blockIdx.x * 256 + threadIdx.x; i < DQ * DQ; i += gridDim.x * 256) {
        {
            const float v = W[i];
            const __half h = __float2half(v);
            whi[i] = h;
            wlo[i] = __float2half(v - __half2float(h));
        }
        {
            const int n = i / DQ, k = i % DQ;
            const float v = attn[(size_t)k * DQ + n];
            const __half h = __float2half(v);
            ahi[i] = h;
            alo[i] = __float2half(v - __half2float(h));
        }
    }
}

// ---------------------------------------------------------------------------
// Row softmax over scores -> P fp16. 256 threads, 8 elems (2x float4, MLP 2).
// ---------------------------------------------------------------------------
__global__ __launch_bounds__(256) void k_softmax(
    const float* __restrict__ S, __half* __restrict__ P)
{
    __shared__ float red[8];
    const size_t base = (size_t)blockIdx.x * NQ;
    const int tid = threadIdx.x;
    const int lane = tid & 31, wid = tid >> 5;

    float4 v0 = *(const float4*)(S + base + tid * 4);
    float4 v1 = *(const float4*)(S + base + 1024 + tid * 4);

    float m = fmaxf(fmaxf(fmaxf(v0.x, v0.y), fmaxf(v0.z, v0.w)),
                    fmaxf(fmaxf(v1.x, v1.y), fmaxf(v1.z, v1.w)));
#pragma unroll
    for (int o = 16; o > 0; o >>= 1)
        m = fmaxf(m, __shfl_xor_sync(0xffffffff, m, o));
    if (lane == 0) red[wid] = m;
    __syncthreads();
    if (wid == 0) {
        float t = red[lane & 7];
#pragma unroll
        for (int o = 4; o > 0; o >>= 1)
            t = fmaxf(t, __shfl_xor_sync(0xffffffff, t, o));
        if (lane == 0) red[0] = t;
    }
    __syncthreads();
    m = red[0];

    v0.x = expf(v0.x - m); v0.y = expf(v0.y - m);
    v0.z = expf(v0.z - m); v0.w = expf(v0.w - m);
    v1.x = expf(v1.x - m); v1.y = expf(v1.y - m);
    v1.z = expf(v1.z - m); v1.w = expf(v1.w - m);
    float s = (v0.x + v0.y + v0.z + v0.w) + (v1.x + v1.y + v1.z + v1.w);
#pragma unroll
    for (int o = 16; o > 0; o >>= 1)
        s += __shfl_xor_sync(0xffffffff, s, o);
    __syncthreads();
    if (lane == 0) red[wid] = s;
    __syncthreads();
    if (wid == 0) {
        float t = red[lane & 7];
#pragma unroll
        for (int o = 4; o > 0; o >>= 1)
            t += __shfl_xor_sync(0xffffffff, t, o);
        if (lane == 0) red[0] = t;
    }
    __syncthreads();
    const float inv = 1.f / red[0];

    __half2* dst0 = (__half2*)(P + base + tid * 4);
    dst0[0] = __floats2half2_rn(v0.x * inv, v0.y * inv);
    dst0[1] = __floats2half2_rn(v0.z * inv, v0.w * inv);
    __half2* dst1 = (__half2*)(P + base + 1024 + tid * 4);
    dst1[0] = __floats2half2_rn(v1.x * inv, v1.y * inv);
    dst1[1] = __floats2half2_rn(v1.z * inv, v1.w * inv);
}

// ---------------------------------------------------------------------------
// Launch
// ---------------------------------------------------------------------------
extern "C" void kernel_launch(void* const* d_in, const int* in_sizes, int n_in,
                              void* d_out, int out_size)
{
    const float* x    = (const float*)d_in[0];
    const int*   adj  = (const int*)  d_in[1];
    const float* W    = (const float*)d_in[2];
    const float* bias = (const float*)d_in[3];
    const float* attn = (const float*)d_in[4];
    float* out = (float*)d_out;

    __half *x_hi, *x_lo, *w_hi, *w_lo, *at_hi, *at_lo;
    __half *h_hi, *h_lo, *ht_hi, *ha_hi, *ha_lo, *p;
    float* s;
    cudaGetSymbolAddress((void**)&x_hi,  g_x_hi);  cudaGetSymbolAddress((void**)&x_lo,  g_x_lo);
    cudaGetSymbolAddress((void**)&w_hi,  g_w_hi);  cudaGetSymbolAddress((void**)&w_lo,  g_w_lo);
    cudaGetSymbolAddress((void**)&at_hi, g_at_hi); cudaGetSymbolAddress((void**)&at_lo, g_at_lo);
    cudaGetSymbolAddress((void**)&h_hi,  g_h_hi);  cudaGetSymbolAddress((void**)&h_lo,  g_h_lo);
    cudaGetSymbolAddress((void**)&ht_hi, g_ht_hi);
    cudaGetSymbolAddress((void**)&ha_hi, g_ha_hi); cudaGetSymbolAddress((void**)&ha_lo, g_ha_lo);
    cudaGetSymbolAddress((void**)&p,     g_p);
    cudaGetSymbolAddress((void**)&s,     g_s);

    cudaFuncSetAttribute(k_mma<1>, cudaFuncAttributeMaxDynamicSharedMemorySize, SMEM_G3P);
    cudaFuncSetAttribute(k_mma<2>, cudaFuncAttributeMaxDynamicSharedMemorySize, SMEM_G3P);
    cudaFuncSetAttribute(k_mma<3>, cudaFuncAttributeMaxDynamicSharedMemorySize, SMEM_G3P);
    cudaFuncSetAttribute(k_mma<4>, cudaFuncAttributeMaxDynamicSharedMemorySize, SMEM_G4);

    // Input splits
    k_split4<<<2048, 256>>>((const float4*)x, (__half2*)x_hi, (__half2*)x_lo,
                            MTOT * DQ / 4);
    k_split_small<<<512, 256>>>(W, w_hi, w_lo, attn, at_hi, at_lo);

    // h = x @ W^T + b  (3-pass), hT_hi produced in epilogue
    k_mma<1><<<dim3(DQ / 128, MTOT / 128, 1), 128, SMEM_G3P>>>(
        x_hi, x_lo, w_hi, w_lo, bias, nullptr, nullptr, h_hi, h_lo, ht_hi);

    // ha = h @ attn  (3-pass)
    k_mma<2><<<dim3(DQ / 128, MTOT / 128, 1), 128, SMEM_G3P>>>(
        h_hi, h_lo, at_hi, at_lo, nullptr, nullptr, nullptr, ha_hi, ha_lo, nullptr);

    // scores = ha @ h^T (per batch), adjacency-masked  (3-pass)
    k_mma<3><<<dim3(NQ / 128, NQ / 128, BQ), 128, SMEM_G3P>>>(
        ha_hi, ha_lo, h_hi, h_lo, nullptr, adj, s, nullptr, nullptr, nullptr);

    // softmax rows -> P fp16
    k_softmax<<<BQ * NQ, 256>>>(s, p);

    // out = elu(P @ h) per batch  (1-pass, 4-stage pipeline)
    k_mma<4><<<dim3(DQ / 128, NQ / 128, BQ), 128, SMEM_G4>>>(
        p, p, ht_hi, ht_hi, nullptr, nullptr, out, nullptr, nullptr, nullptr);
}

// round 14
// speedup vs baseline: 1.1421x; 1.0006x over previous
#include <cuda_runtime.h>
#include <cuda_fp16.h>
#include <cstdint>
#include <math.h>

// ---------------------------------------------------------------------------
// Problem constants
// ---------------------------------------------------------------------------
#define BQ 8
#define NQ 2048
#define DQ 512
#define MTOT (BQ * NQ)   // 16384
#define NTILE 16         // score col-tiles per row (2048/128)

// ---------------------------------------------------------------------------
// Device scratch (no runtime allocation allowed)
// ---------------------------------------------------------------------------
__device__ __half g_x_hi[MTOT * DQ], g_x_lo[MTOT * DQ];
__device__ __half g_w_hi[DQ * DQ],   g_w_lo[DQ * DQ];
__device__ __half g_at_hi[DQ * DQ],  g_at_lo[DQ * DQ];     // attn^T
__device__ __half g_h_hi[MTOT * DQ],  g_h_lo[MTOT * DQ];
__device__ __half g_ht_hi[MTOT * DQ];                      // per-batch H^T (hi only)
__device__ __half g_ha_hi[MTOT * DQ], g_ha_lo[MTOT * DQ];
__device__ __half g_e[(size_t)BQ * NQ * NQ];               // E = exp(s - m_t), fp16
__device__ float g_mt[(size_t)BQ * NQ * NTILE];            // per-(row,tile) max
__device__ float g_st[(size_t)BQ * NQ * NTILE];            // per-(row,tile) sum

// ---------------------------------------------------------------------------
// Low-level helpers (base compute_103 features only)
// ---------------------------------------------------------------------------
__device__ __forceinline__ uint32_t smem_u32(const void* p) {
    uint32_t a;
    asm("{ .reg .u64 t; cvta.to.shared.u64 t, %1; cvt.u32.u64 %0, t; }" : "=r"(a) : "l"(p));
    return a;
}

#define CP16(dst, src) \
    asm volatile("cp.async.cg.shared.global [%0], [%1], 16;\n" :: "r"(dst), "l"(src) : "memory")
#define CP_COMMIT() asm volatile("cp.async.commit_group;\n" ::: "memory")
#define CP_WAIT1()  asm volatile("cp.async.wait_group 1;\n" ::: "memory")
#define CP_WAIT2()  asm volatile("cp.async.wait_group 2;\n" ::: "memory")

__device__ __forceinline__ void ldsm4(uint32_t* r, uint32_t addr) {
    asm volatile("ldmatrix.sync.aligned.m8n8.x4.shared.b16 {%0,%1,%2,%3}, [%4];\n"
                 : "=r"(r[0]), "=r"(r[1]), "=r"(r[2]), "=r"(r[3]) : "r"(addr));
}

__device__ __forceinline__ void mma16816(float* c, const uint32_t* a, const uint32_t* b) {
    asm volatile(
        "mma.sync.aligned.m16n8k16.row.col.f32.f16.f16.f32 "
        "{%0,%1,%2,%3}, {%4,%5,%6,%7}, {%8,%9}, {%0,%1,%2,%3};\n"
        : "+f"(c[0]), "+f"(c[1]), "+f"(c[2]), "+f"(c[3])
        : "r"(a[0]), "r"(a[1]), "r"(a[2]), "r"(a[3]), "r"(b[0]), "r"(b[1]));
}

__device__ __forceinline__ uint32_t mulh2(uint32_t x, __half2 a) {
    __half2 v = *(__half2*)&x;
    v = __hmul2(v, a);
    return *(uint32_t*)&v;
}

// ---------------------------------------------------------------------------
// Unified HMMA GEMM: C[m,n] = sum_k A[m,k] * B[n,k] via fp16 split
// CTA tile 128x128, 128 threads = 4 warps (2M x 2N), warp 64x64, fp32 acc,
// pass-major inner loop (R10/R13 champion mainloop).
// MODES 1-3: 3-pass (hh+hl+lh), 3-stage pipeline.
// MODE 4:    1-pass, 4-stage pipeline, A-fragments scaled per-(row,tile) by
//            alpha = exp(m_t - M)/L computed in-kernel from (m_t, S_t).
// MODE 1: out = C + bias -> h hi/lo + fused hT_hi   (M=16384,N=512,K=512)
// MODE 2: out = C        -> ha hi/lo                 (M=16384,N=512,K=512)
// MODE 3: masked exp with per-(row,tile) max: writes E fp16 + m_t + S_t
//         (per batch, M=N=2048, K=512)
// MODE 4: out = elu( sum_t alpha_t * E_t @ h_t ) -> fp32
//         (per batch, M=2048, N=512, K=2048)
// ---------------------------------------------------------------------------
template <int MODE>
__global__ __launch_bounds__(128, 2) void k_mma(
    const __half* __restrict__ Ahi, const __half* __restrict__ Alo,
    const __half* __restrict__ Bhi, const __half* __restrict__ Blo,
    const float* __restrict__ bias, const int* __restrict__ adj,
    float* __restrict__ outf,
    __half* __restrict__ out_hi, __half* __restrict__ out_lo,
    __half* __restrict__ out_t,
    float* __restrict__ statm, float* __restrict__ stats)
{
    constexpr bool SPL  = (MODE != 4);
    constexpr int KDIM = (MODE == 4) ? 2048 : 512;
    constexpr int LDA  = (MODE == 4) ? 2048 : 512;
    constexpr int LDB  = (MODE == 4) ? 2048 : 512;
    constexpr int NST  = KDIM / 32;
    constexpr int ASB  = SPL ? 16384 : 8192;
    constexpr int BSB  = SPL ? 16384 : 8192;
    constexpr int STG  = ASB + BSB;
    constexpr int NSTG = SPL ? 3 : 4;

    extern __shared__ char smem[];
    const uint32_t sbase = smem_u32(smem);
    const int tid = threadIdx.x;
    const int lane = tid & 31, wid = tid >> 5;
    const int warp_m = wid & 1;
    const int warp_n = wid >> 1;

    const int bn = blockIdx.x * 128, bm = blockIdx.y * 128, z = blockIdx.z;
    size_t aoff = 0, boff = 0;
    if (MODE == 3) { aoff = (size_t)z * NQ * DQ; boff = (size_t)z * NQ * DQ; }
    if (MODE == 4) { aoff = (size_t)z * NQ * NQ; boff = (size_t)z * DQ * NQ; }

    const char* A0h = (const char*)(Ahi + aoff + (size_t)bm * LDA);
    const char* A0l = (const char*)(Alo + aoff + (size_t)bm * LDA);
    const char* B0h = (const char*)(Bhi + boff + (size_t)bn * LDB);
    const char* B0l = (const char*)(Blo + boff + (size_t)bn * LDB);

    // MODE 4: compute per-(row, tile) alpha into smem (after the 4 stages)
    __half* s_alpha = (__half*)(smem + 4 * 16384);   // [NTILE][128] half
    if (MODE == 4) {
        const size_t rb = ((size_t)z * NQ + bm + tid) * NTILE;
        float mtv[NTILE], ex[NTILE];
        float M = -1e30f;
#pragma unroll
        for (int t = 0; t < NTILE; ++t) { mtv[t] = statm[rb + t]; M = fmaxf(M, mtv[t]); }
        float L = 0.f;
#pragma unroll
        for (int t = 0; t < NTILE; ++t) { ex[t] = expf(mtv[t] - M); L += ex[t] * stats[rb + t]; }
        const float invL = 1.f / L;
#pragma unroll
        for (int t = 0; t < NTILE; ++t)
            s_alpha[t * 128 + tid] = __float2half(ex[t] * invL);
    }

    auto issue_stage = [&](uint32_t sd, int kb) {
        if (SPL) {
            const uint32_t row0 = tid >> 3;
            const uint32_t c = tid & 7;
            const uint32_t off = c * 16;
            const char* srcA = (c < 4) ? A0h : A0l;
            const char* srcB = (c < 4) ? B0h : B0l;
            const int cb = (c & 3) * 16;
#pragma unroll
            for (int blk = 0; blk < 8; ++blk) {
                const uint32_t row = row0 + blk * 16;
                const uint32_t sw = row * 128 + (off ^ ((row & 7) << 4));
                CP16(sd + sw,       srcA + (size_t)row * (LDA * 2) + kb + cb);
                CP16(sd + ASB + sw, srcB + (size_t)row * (LDB * 2) + kb + cb);
            }
        } else {
            const uint32_t row0 = tid >> 2;
            const uint32_t c = tid & 3;
            const uint32_t off = c * 16;
#pragma unroll
            for (int blk = 0; blk < 4; ++blk) {
                const uint32_t row = row0 + blk * 32;
                const uint32_t sw = row * 64 + (off ^ ((row & 3) << 4));
                CP16(sd + sw,       A0h + (size_t)row * (LDA * 2) + kb + c * 16);
                CP16(sd + ASB + sw, B0h + (size_t)row * (LDB * 2) + kb + c * 16);
            }
        }
    };

    uint32_t a_rt[4], a_sw[4];
#pragma unroll
    for (int mi = 0; mi < 4; ++mi) {
        const uint32_t r = warp_m * 64 + mi * 16 + (lane & 15);
        if (SPL) { a_rt[mi] = r * 128; a_sw[mi] = (r & 7) << 4; }
        else     { a_rt[mi] = r * 64;  a_sw[mi] = (r & 3) << 4; }
    }
    uint32_t b_rt[4], b_sw[4];
    {
        const uint32_t brow = (lane & 7) + ((lane >> 4) & 1) * 8;
#pragma unroll
        for (int jp = 0; jp < 4; ++jp) {
            const uint32_t r = warp_n * 64 + jp * 16 + brow;
            if (SPL) { b_rt[jp] = r * 128; b_sw[jp] = (r & 7) << 4; }
            else     { b_rt[jp] = r * 64;  b_sw[jp] = (r & 3) << 4; }
        }
    }
    const uint32_t a_koff = (lane >> 4) * 16;
    const uint32_t b_koff = ((lane >> 3) & 1) * 16;

    float acc[4][8][4];
#pragma unroll
    for (int i = 0; i < 4; ++i)
#pragma unroll
        for (int j = 0; j < 8; ++j)
#pragma unroll
            for (int k = 0; k < 4; ++k) acc[i][j][k] = 0.f;

#pragma unroll
    for (int sgi = 0; sgi < NSTG - 1; ++sgi) {
        issue_stage(sbase + sgi * STG, sgi * 64);
        CP_COMMIT();
    }

    int buf = 0, nbuf = NSTG - 1;
    for (int i = 0; i < NST; ++i) {
        if (SPL) { CP_WAIT1(); } else { CP_WAIT2(); }
        __syncthreads();
        if (i + NSTG - 1 < NST)
            issue_stage(sbase + nbuf * STG, (i + NSTG - 1) * 64);
        CP_COMMIT();

        const uint32_t sa = sbase + buf * STG;
        const uint32_t sb = sa + ASB;
#pragma unroll
        for (int ks = 0; ks < 2; ++ks) {
            const uint32_t ko = ks * 32;
            uint32_t ah[4][4], al[4][4], bh[4][4], bl[4][4];
#pragma unroll
            for (int mi = 0; mi < 4; ++mi) {
                ldsm4(ah[mi], sa + a_rt[mi] + ((ko + a_koff) ^ a_sw[mi]));
                if (SPL)
                    ldsm4(al[mi], sa + a_rt[mi] + ((ko + a_koff + 64) ^ a_sw[mi]));
            }
            if (!SPL) {
                // scale A fragments (rows of E) by alpha[row][tile]
                const int tt = i >> 2;
#pragma unroll
                for (int mi = 0; mi < 4; ++mi) {
                    const int r0 = warp_m * 64 + mi * 16 + (lane >> 2);
                    const __half2 a0 = __half2half2(s_alpha[tt * 128 + r0]);
                    const __half2 a1 = __half2half2(s_alpha[tt * 128 + r0 + 8]);
                    ah[mi][0] = mulh2(ah[mi][0], a0);
                    ah[mi][2] = mulh2(ah[mi][2], a0);
                    ah[mi][1] = mulh2(ah[mi][1], a1);
                    ah[mi][3] = mulh2(ah[mi][3], a1);
                }
            }
#pragma unroll
            for (int jp = 0; jp < 4; ++jp) {
                ldsm4(bh[jp], sb + b_rt[jp] + ((ko + b_koff) ^ b_sw[jp]));
                if (SPL)
                    ldsm4(bl[jp], sb + b_rt[jp] + ((ko + b_koff + 64) ^ b_sw[jp]));
            }
#pragma unroll
            for (int mi = 0; mi < 4; ++mi)
#pragma unroll
                for (int jp = 0; jp < 4; ++jp) {
                    mma16816(acc[mi][2*jp],   ah[mi], bh[jp]);
                    mma16816(acc[mi][2*jp+1], ah[mi], bh[jp] + 2);
                }
            if (SPL) {
#pragma unroll
                for (int mi = 0; mi < 4; ++mi)
#pragma unroll
                    for (int jp = 0; jp < 4; ++jp) {
                        mma16816(acc[mi][2*jp],   ah[mi], bl[jp]);
                        mma16816(acc[mi][2*jp+1], ah[mi], bl[jp] + 2);
                    }
#pragma unroll
                for (int mi = 0; mi < 4; ++mi)
#pragma unroll
                    for (int jp = 0; jp < 4; ++jp) {
                        mma16816(acc[mi][2*jp],   al[mi], bh[jp]);
                        mma16816(acc[mi][2*jp+1], al[mi], bh[jp] + 2);
                    }
            }
        }
        buf = (buf == NSTG - 1) ? 0 : buf + 1;
        nbuf = (nbuf == NSTG - 1) ? 0 : nbuf + 1;
    }

    // -----------------------------------------------------------------------
    // Epilogue
    // -----------------------------------------------------------------------
    const int rbase = bm + warp_m * 64 + (lane >> 2);
    const int cbase = bn + warp_n * 64 + (lane & 3) * 2;

    if (MODE == 1 || MODE == 2) {
        __half* st = (__half*)(smem + STG);   // MODE1 transpose staging
        if (MODE == 1) __syncthreads();
#pragma unroll
        for (int mi = 0; mi < 4; ++mi)
#pragma unroll
            for (int j = 0; j < 8; ++j) {
                const int gc = cbase + j * 8;
#pragma unroll
                for (int half = 0; half < 2; ++half) {
                    const int gr = rbase + mi * 16 + half * 8;
                    float v0 = acc[mi][j][half * 2 + 0];
                    float v1 = acc[mi][j][half * 2 + 1];
                    if (MODE == 1) {
                        const float2 bv = *(const float2*)(bias + gc);
                        v0 += bv.x; v1 += bv.y;
                    }
                    const __half h0 = __float2half(v0);
                    const __half h1 = __float2half(v1);
                    __half2 hp; hp.x = h0; hp.y = h1;
                    __half2 lp;
                    lp.x = __float2half(v0 - __half2float(h0));
                    lp.y = __float2half(v1 - __half2float(h1));
                    *(__half2*)(out_hi + (size_t)gr * DQ + gc) = hp;
                    *(__half2*)(out_lo + (size_t)gr * DQ + gc) = lp;
                    if (MODE == 1) {
                        st[(gc - bn)     * 136 + (gr - bm)] = h0;
                        st[(gc + 1 - bn) * 136 + (gr - bm)] = h1;
                    }
                }
            }
        if (MODE == 1) {
            __syncthreads();
            const int b = bm >> 11, n0 = bm & 2047;
            const __half* src = st + tid * 136;
            __half* dst = out_t + ((size_t)(b * DQ + bn + tid)) * NQ + n0;
#pragma unroll
            for (int k2 = 0; k2 < 16; ++k2)
                *(float4*)(dst + k2 * 8) = *(const float4*)(src + k2 * 8);
        }
    } else if (MODE == 3) {
        // mask -> per-(row,tile) max -> E = exp(s - m_t) -> sums -> write
        __syncthreads();
        float* red = (float*)smem;   // [128 local rows][2 warp_n]
        // 1) adjacency mask
#pragma unroll
        for (int mi = 0; mi < 4; ++mi)
#pragma unroll
            for (int j = 0; j < 8; ++j)
#pragma unroll
                for (int half = 0; half < 2; ++half) {
                    const int gr = rbase + mi * 16 + half * 8;
                    const int gc = cbase + j * 8;
                    const size_t o = (size_t)z * NQ * NQ + (size_t)gr * NQ + gc;
                    const int2 ad = *(const int2*)(adj + o);
                    if (!ad.x) acc[mi][j][half * 2]     = -1e30f;
                    if (!ad.y) acc[mi][j][half * 2 + 1] = -1e30f;
                }
        // 2) row-tile max (in-thread -> shfl over lane&3 -> cross warp_n via smem)
        float mt[4][2];
#pragma unroll
        for (int mi = 0; mi < 4; ++mi)
#pragma unroll
            for (int half = 0; half < 2; ++half) {
                float m = -1e30f;
#pragma unroll
                for (int j = 0; j < 8; ++j)
                    m = fmaxf(m, fmaxf(acc[mi][j][half*2], acc[mi][j][half*2+1]));
                m = fmaxf(m, __shfl_xor_sync(0xffffffffu, m, 1));
                m = fmaxf(m, __shfl_xor_sync(0xffffffffu, m, 2));
                if ((lane & 3) == 0)
                    red[(warp_m*64 + mi*16 + half*8 + (lane>>2)) * 2 + warp_n] = m;
            }
        __syncthreads();
#pragma unroll
        for (int mi = 0; mi < 4; ++mi)
#pragma unroll
            for (int half = 0; half < 2; ++half) {
                const int rl = warp_m*64 + mi*16 + half*8 + (lane>>2);
                mt[mi][half] = fmaxf(red[rl*2], red[rl*2+1]);
            }
        __syncthreads();
        // 3) exp + row-tile sums
#pragma unroll
        for (int mi = 0; mi < 4; ++mi)
#pragma unroll
            for (int half = 0; half < 2; ++half) {
                const float m = mt[mi][half];
                float ssum = 0.f;
#pragma unroll
                for (int j = 0; j < 8; ++j) {
                    const float e0 = expf(acc[mi][j][half*2]     - m);
                    const float e1 = expf(acc[mi][j][half*2 + 1] - m);
                    acc[mi][j][half*2]     = e0;
                    acc[mi][j][half*2 + 1] = e1;
                    ssum += e0 + e1;
                }
                ssum += __shfl_xor_sync(0xffffffffu, ssum, 1);
                ssum += __shfl_xor_sync(0xffffffffu, ssum, 2);
                if ((lane & 3) == 0)
                    red[(warp_m*64 + mi*16 + half*8 + (lane>>2)) * 2 + warp_n] = ssum;
            }
        __syncthreads();
        // 4) write E (fp16) and stats
#pragma unroll
        for (int mi = 0; mi < 4; ++mi)
#pragma unroll
            for (int j = 0; j < 8; ++j)
#pragma unroll
                for (int half = 0; half < 2; ++half) {
                    const int gr = rbase + mi * 16 + half * 8;
                    const int gc = cbase + j * 8;
                    const size_t o = (size_t)z * NQ * NQ + (size_t)gr * NQ + gc;
                    *(__half2*)(out_hi + o) =
                        __floats2half2_rn(acc[mi][j][half*2], acc[mi][j][half*2+1]);
                }
        if (warp_n == 0 && (lane & 3) == 0) {
#pragma unroll
            for (int mi = 0; mi < 4; ++mi)
#pragma unroll
                for (int half = 0; half < 2; ++half) {
                    const int gr = rbase + mi * 16 + half * 8;
                    const int rl = warp_m*64 + mi*16 + half*8 + (lane>>2);
                    const size_t idx = ((size_t)z * NQ + gr) * NTILE + blockIdx.x;
                    statm[idx] = mt[mi][half];
                    stats[idx] = red[rl*2] + red[rl*2+1];
                }
        }
    } else {
        // MODE 4: elu
#pragma unroll
        for (int mi = 0; mi < 4; ++mi)
#pragma unroll
            for (int j = 0; j < 8; ++j) {
                const int gc = cbase + j * 8;
#pragma unroll
                for (int half = 0; half < 2; ++half) {
                    const int gr = rbase + mi * 16 + half * 8;
                    const float v0 = acc[mi][j][half * 2 + 0];
                    const float v1 = acc[mi][j][half * 2 + 1];
                    const size_t o = (size_t)z * NQ * DQ + (size_t)gr * DQ + gc;
                    float2 ov;
                    ov.x = (v0 > 0.f) ? v0 : expm1f(v0);
                    ov.y = (v1 > 0.f) ? v1 : expm1f(v1);
                    *(float2*)(outf + o) = ov;
                }
            }
    }
}

#define SMEM_G3P (3 * 32768)             // MODE 1/2/3: 98304
#define SMEM_G4  (4 * 16384 + 4096)      // MODE 4: 69632 (stages + alpha)

// ---------------------------------------------------------------------------
// fp32 -> fp16 hi/lo split, vectorized
// ---------------------------------------------------------------------------
__global__ __launch_bounds__(256) void k_split4(
    const float4* __restrict__ in, __half2* __restrict__ hi,
    __half2* __restrict__ lo, int n4)
{
    for (int i = blockIdx.x * 256 + threadIdx.x; i < n4; i += gridDim.x * 256) {
        const float4 v = in[i];
        const __half2 h0 = __floats2half2_rn(v.x, v.y);
        const __half2 h1 = __floats2half2_rn(v.z, v.w);
        const float2 f0 = __half22float2(h0);
        const float2 f1 = __half22float2(h1);
        hi[2*i]   = h0;
        hi[2*i+1] = h1;
        lo[2*i]   = __floats2half2_rn(v.x - f0.x, v.y - f0.y);
        lo[2*i+1] = __floats2half2_rn(v.z - f1.x, v.w - f1.y);
    }
}

// Merged small splits: W (elementwise) and attn (transposed), both DQxDQ.
__global__ __launch_bounds__(256) void k_split_small(
    const float* __restrict__ W, __half* __restrict__ whi, __half* __restrict__ wlo,
    const float* __restrict__ attn, __half* __restrict__ ahi, __half* __restrict__ alo)
{
    for (int i = blockIdx.x * 256 + threadIdx.x; i < DQ * DQ; i += gridDim.x * 256) {
        {
            const float v = W[i];
            const __half h = __float2half(v);
            whi[i] = h;
            wlo[i] = __float2half(v - __half2float(h));
        }
        {
            const int n = i / DQ, k = i % DQ;
            const float v = attn[(size_t)k * DQ + n];
            const __half h = __float2half(v);
            ahi[i] = h;
            alo[i] = __float2half(v - __half2float(h));
        }
    }
}

// ---------------------------------------------------------------------------
// Launch
// ---------------------------------------------------------------------------
extern "C" void kernel_launch(void* const* d_in, const int* in_sizes, int n_in,
                              void* d_out, int out_size)
{
    const float* x    = (const float*)d_in[0];
    const int*   adj  = (const int*)  d_in[1];
    const float* W    = (const float*)d_in[2];
    const float* bias = (const float*)d_in[3];
    const float* attn = (const float*)d_in[4];
    float* out = (float*)d_out;

    __half *x_hi, *x_lo, *w_hi, *w_lo, *at_hi, *at_lo;
    __half *h_hi, *h_lo, *ht_hi, *ha_hi, *ha_lo, *e;
    float *mt, *st;
    cudaGetSymbolAddress((void**)&x_hi,  g_x_hi);  cudaGetSymbolAddress((void**)&x_lo,  g_x_lo);
    cudaGetSymbolAddress((void**)&w_hi,  g_w_hi);  cudaGetSymbolAddress((void**)&w_lo,  g_w_lo);
    cudaGetSymbolAddress((void**)&at_hi, g_at_hi); cudaGetSymbolAddress((void**)&at_lo, g_at_lo);
    cudaGetSymbolAddress((void**)&h_hi,  g_h_hi);  cudaGetSymbolAddress((void**)&h_lo,  g_h_lo);
    cudaGetSymbolAddress((void**)&ht_hi, g_ht_hi);
    cudaGetSymbolAddress((void**)&ha_hi, g_ha_hi); cudaGetSymbolAddress((void**)&ha_lo, g_ha_lo);
    cudaGetSymbolAddress((void**)&e,     g_e);
    cudaGetSymbolAddress((void**)&mt,    g_mt);
    cudaGetSymbolAddress((void**)&st,    g_st);

    cudaFuncSetAttribute(k_mma<1>, cudaFuncAttributeMaxDynamicSharedMemorySize, SMEM_G3P);
    cudaFuncSetAttribute(k_mma<2>, cudaFuncAttributeMaxDynamicSharedMemorySize, SMEM_G3P);
    cudaFuncSetAttribute(k_mma<3>, cudaFuncAttributeMaxDynamicSharedMemorySize, SMEM_G3P);
    cudaFuncSetAttribute(k_mma<4>, cudaFuncAttributeMaxDynamicSharedMemorySize, SMEM_G4);

    // Input splits
    k_split4<<<2048, 256>>>((const float4*)x, (__half2*)x_hi, (__half2*)x_lo,
                            MTOT * DQ / 4);
    k_split_small<<<512, 256>>>(W, w_hi, w_lo, attn, at_hi, at_lo);

    // h = x @ W^T + b  (3-pass), hT_hi produced in epilogue
    k_mma<1><<<dim3(DQ / 128, MTOT / 128, 1), 128, SMEM_G3P>>>(
        x_hi, x_lo, w_hi, w_lo, bias, nullptr, nullptr, h_hi, h_lo, ht_hi,
        nullptr, nullptr);

    // ha = h @ attn  (3-pass)
    k_mma<2><<<dim3(DQ / 128, MTOT / 128, 1), 128, SMEM_G3P>>>(
        h_hi, h_lo, at_hi, at_lo, nullptr, nullptr, nullptr, ha_hi, ha_lo, nullptr,
        nullptr, nullptr);

    // scores -> masked exp tiles: E fp16 + (m_t, S_t)  (3-pass, fused softmax part 1)
    k_mma<3><<<dim3(NQ / 128, NQ / 128, BQ), 128, SMEM_G3P>>>(
        ha_hi, ha_lo, h_hi, h_lo, nullptr, adj, nullptr, e, nullptr, nullptr,
        mt, st);

    // out = elu( sum_t alpha_t E_t @ h ) per batch  (1-pass, fused softmax part 2)
    k_mma<4><<<dim3(DQ / 128, NQ / 128, BQ), 128, SMEM_G4>>>(
        e, e, ht_hi, ht_hi, nullptr, nullptr, out, nullptr, nullptr, nullptr,
        mt, st);
}

// round 15
// speedup vs baseline: 1.1547x; 1.0111x over previous
#include <cuda_runtime.h>
#include <cuda_fp16.h>
#include <cstdint>
#include <math.h>

// ---------------------------------------------------------------------------
// Problem constants
// ---------------------------------------------------------------------------
#define BQ 8
#define NQ 2048
#define DQ 512
#define MTOT (BQ * NQ)   // 16384
#define NTILE 32         // score col-tiles per row (2048/64), one per warp_n

// ---------------------------------------------------------------------------
// Device scratch (no runtime allocation allowed)
// ---------------------------------------------------------------------------
__device__ __half g_x_hi[MTOT * DQ], g_x_lo[MTOT * DQ];
__device__ __half g_w_hi[DQ * DQ],   g_w_lo[DQ * DQ];
__device__ __half g_at_hi[DQ * DQ],  g_at_lo[DQ * DQ];     // attn^T
__device__ __half g_h_hi[MTOT * DQ],  g_h_lo[MTOT * DQ];
__device__ __half g_ht_hi[MTOT * DQ];                      // per-batch H^T (hi only)
__device__ __half g_ha_hi[MTOT * DQ], g_ha_lo[MTOT * DQ];
__device__ __half g_e[(size_t)BQ * NQ * NQ];               // E = exp(s - m_t), fp16
__device__ float g_mt[(size_t)NTILE * MTOT];               // [tile][row] max
__device__ float g_st[(size_t)NTILE * MTOT];               // [tile][row] sum

// ---------------------------------------------------------------------------
// Low-level helpers (base compute_103 features only)
// ---------------------------------------------------------------------------
__device__ __forceinline__ uint32_t smem_u32(const void* p) {
    uint32_t a;
    asm("{ .reg .u64 t; cvta.to.shared.u64 t, %1; cvt.u32.u64 %0, t; }" : "=r"(a) : "l"(p));
    return a;
}

#define CP16(dst, src) \
    asm volatile("cp.async.cg.shared.global [%0], [%1], 16;\n" :: "r"(dst), "l"(src) : "memory")
#define CP_COMMIT() asm volatile("cp.async.commit_group;\n" ::: "memory")
#define CP_WAIT1()  asm volatile("cp.async.wait_group 1;\n" ::: "memory")
#define CP_WAIT2()  asm volatile("cp.async.wait_group 2;\n" ::: "memory")

__device__ __forceinline__ void ldsm4(uint32_t* r, uint32_t addr) {
    asm volatile("ldmatrix.sync.aligned.m8n8.x4.shared.b16 {%0,%1,%2,%3}, [%4];\n"
                 : "=r"(r[0]), "=r"(r[1]), "=r"(r[2]), "=r"(r[3]) : "r"(addr));
}

__device__ __forceinline__ void mma16816(float* c, const uint32_t* a, const uint32_t* b) {
    asm volatile(
        "mma.sync.aligned.m16n8k16.row.col.f32.f16.f16.f32 "
        "{%0,%1,%2,%3}, {%4,%5,%6,%7}, {%8,%9}, {%0,%1,%2,%3};\n"
        : "+f"(c[0]), "+f"(c[1]), "+f"(c[2]), "+f"(c[3])
        : "r"(a[0]), "r"(a[1]), "r"(a[2]), "r"(a[3]), "r"(b[0]), "r"(b[1]));
}

__device__ __forceinline__ uint32_t mulh2(uint32_t x, __half2 a) {
    __half2 v = *(__half2*)&x;
    v = __hmul2(v, a);
    return *(uint32_t*)&v;
}

// ---------------------------------------------------------------------------
// Unified HMMA GEMM: C[m,n] = sum_k A[m,k] * B[n,k] via fp16 split
// CTA tile 128x128, 128 threads = 4 warps (2M x 2N), warp 64x64, fp32 acc,
// pass-major inner loop.
// MODES 1-3: 3-pass (hh+hl+lh), 3-stage pipeline.
// MODE 4:    1-pass, 4-stage pipeline, A-fragments scaled per-(row,64-tile)
//            by alpha = exp(m_t - M)/L computed in-kernel from (m_t, S_t).
// MODE 1: out = C + bias -> h hi/lo + fused hT_hi   (M=16384,N=512,K=512)
// MODE 2: out = C        -> ha hi/lo                 (M=16384,N=512,K=512)
// MODE 3: masked exp, per-(row, warp_n 64-col tile) max: E fp16 + m_t + S_t
//         (all reductions shfl-only, zero epilogue barriers)
// MODE 4: out = elu( sum_t alpha_t * E_t @ h_t ) -> fp32
// ---------------------------------------------------------------------------
template <int MODE>
__global__ __launch_bounds__(128, 2) void k_mma(
    const __half* __restrict__ Ahi, const __half* __restrict__ Alo,
    const __half* __restrict__ Bhi, const __half* __restrict__ Blo,
    const float* __restrict__ bias, const int* __restrict__ adj,
    float* __restrict__ outf,
    __half* __restrict__ out_hi, __half* __restrict__ out_lo,
    __half* __restrict__ out_t,
    float* __restrict__ statm, float* __restrict__ stats)
{
    constexpr bool SPL  = (MODE != 4);
    constexpr int KDIM = (MODE == 4) ? 2048 : 512;
    constexpr int LDA  = (MODE == 4) ? 2048 : 512;
    constexpr int LDB  = (MODE == 4) ? 2048 : 512;
    constexpr int NST  = KDIM / 32;
    constexpr int ASB  = SPL ? 16384 : 8192;
    constexpr int BSB  = SPL ? 16384 : 8192;
    constexpr int STG  = ASB + BSB;
    constexpr int NSTG = SPL ? 3 : 4;

    extern __shared__ char smem[];
    const uint32_t sbase = smem_u32(smem);
    const int tid = threadIdx.x;
    const int lane = tid & 31, wid = tid >> 5;
    const int warp_m = wid & 1;
    const int warp_n = wid >> 1;

    const int bn = blockIdx.x * 128, bm = blockIdx.y * 128, z = blockIdx.z;
    size_t aoff = 0, boff = 0;
    if (MODE == 3) { aoff = (size_t)z * NQ * DQ; boff = (size_t)z * NQ * DQ; }
    if (MODE == 4) { aoff = (size_t)z * NQ * NQ; boff = (size_t)z * DQ * NQ; }

    const char* A0h = (const char*)(Ahi + aoff + (size_t)bm * LDA);
    const char* A0l = (const char*)(Alo + aoff + (size_t)bm * LDA);
    const char* B0h = (const char*)(Bhi + boff + (size_t)bn * LDB);
    const char* B0l = (const char*)(Blo + boff + (size_t)bn * LDB);

    // MODE 4: per-(row, 64-tile) alpha into smem (placed after the 4 stages).
    // stats layout [tile][row] -> coalesced loads.
    __half* s_alpha = (__half*)(smem + 4 * 16384);   // [NTILE][128] half
    if (MODE == 4) {
        const int rowbase = z * NQ + bm + tid;
        float M = -1e30f;
#pragma unroll
        for (int t = 0; t < NTILE; ++t)
            M = fmaxf(M, statm[(size_t)t * MTOT + rowbase]);
        float L = 0.f;
#pragma unroll
        for (int t = 0; t < NTILE; ++t)
            L += __expf(statm[(size_t)t * MTOT + rowbase] - M) *
                 stats[(size_t)t * MTOT + rowbase];
        const float invL = 1.f / L;
#pragma unroll
        for (int t = 0; t < NTILE; ++t)
            s_alpha[t * 128 + tid] =
                __float2half(__expf(statm[(size_t)t * MTOT + rowbase] - M) * invL);
    }

    auto issue_stage = [&](uint32_t sd, int kb) {
        if (SPL) {
            const uint32_t row0 = tid >> 3;
            const uint32_t c = tid & 7;
            const uint32_t off = c * 16;
            const char* srcA = (c < 4) ? A0h : A0l;
            const char* srcB = (c < 4) ? B0h : B0l;
            const int cb = (c & 3) * 16;
#pragma unroll
            for (int blk = 0; blk < 8; ++blk) {
                const uint32_t row = row0 + blk * 16;
                const uint32_t sw = row * 128 + (off ^ ((row & 7) << 4));
                CP16(sd + sw,       srcA + (size_t)row * (LDA * 2) + kb + cb);
                CP16(sd + ASB + sw, srcB + (size_t)row * (LDB * 2) + kb + cb);
            }
        } else {
            const uint32_t row0 = tid >> 2;
            const uint32_t c = tid & 3;
            const uint32_t off = c * 16;
#pragma unroll
            for (int blk = 0; blk < 4; ++blk) {
                const uint32_t row = row0 + blk * 32;
                const uint32_t sw = row * 64 + (off ^ ((row & 3) << 4));
                CP16(sd + sw,       A0h + (size_t)row * (LDA * 2) + kb + c * 16);
                CP16(sd + ASB + sw, B0h + (size_t)row * (LDB * 2) + kb + c * 16);
            }
        }
    };

    uint32_t a_rt[4], a_sw[4];
#pragma unroll
    for (int mi = 0; mi < 4; ++mi) {
        const uint32_t r = warp_m * 64 + mi * 16 + (lane & 15);
        if (SPL) { a_rt[mi] = r * 128; a_sw[mi] = (r & 7) << 4; }
        else     { a_rt[mi] = r * 64;  a_sw[mi] = (r & 3) << 4; }
    }
    uint32_t b_rt[4], b_sw[4];
    {
        const uint32_t brow = (lane & 7) + ((lane >> 4) & 1) * 8;
#pragma unroll
        for (int jp = 0; jp < 4; ++jp) {
            const uint32_t r = warp_n * 64 + jp * 16 + brow;
            if (SPL) { b_rt[jp] = r * 128; b_sw[jp] = (r & 7) << 4; }
            else     { b_rt[jp] = r * 64;  b_sw[jp] = (r & 3) << 4; }
        }
    }
    const uint32_t a_koff = (lane >> 4) * 16;
    const uint32_t b_koff = ((lane >> 3) & 1) * 16;

    float acc[4][8][4];
#pragma unroll
    for (int i = 0; i < 4; ++i)
#pragma unroll
        for (int j = 0; j < 8; ++j)
#pragma unroll
            for (int k = 0; k < 4; ++k) acc[i][j][k] = 0.f;

#pragma unroll
    for (int sgi = 0; sgi < NSTG - 1; ++sgi) {
        issue_stage(sbase + sgi * STG, sgi * 64);
        CP_COMMIT();
    }

    int buf = 0, nbuf = NSTG - 1;
    for (int i = 0; i < NST; ++i) {
        if (SPL) { CP_WAIT1(); } else { CP_WAIT2(); }
        __syncthreads();
        if (i + NSTG - 1 < NST)
            issue_stage(sbase + nbuf * STG, (i + NSTG - 1) * 64);
        CP_COMMIT();

        const uint32_t sa = sbase + buf * STG;
        const uint32_t sb = sa + ASB;
#pragma unroll
        for (int ks = 0; ks < 2; ++ks) {
            const uint32_t ko = ks * 32;
            uint32_t ah[4][4], al[4][4], bh[4][4], bl[4][4];
#pragma unroll
            for (int mi = 0; mi < 4; ++mi) {
                ldsm4(ah[mi], sa + a_rt[mi] + ((ko + a_koff) ^ a_sw[mi]));
                if (SPL)
                    ldsm4(al[mi], sa + a_rt[mi] + ((ko + a_koff + 64) ^ a_sw[mi]));
            }
            if (!SPL) {
                // scale A fragments (rows of E) by alpha[row][64-tile]
                const int tt = i >> 1;
#pragma unroll
                for (int mi = 0; mi < 4; ++mi) {
                    const int r0 = warp_m * 64 + mi * 16 + (lane >> 2);
                    const __half2 a0 = __half2half2(s_alpha[tt * 128 + r0]);
                    const __half2 a1 = __half2half2(s_alpha[tt * 128 + r0 + 8]);
                    ah[mi][0] = mulh2(ah[mi][0], a0);
                    ah[mi][2] = mulh2(ah[mi][2], a0);
                    ah[mi][1] = mulh2(ah[mi][1], a1);
                    ah[mi][3] = mulh2(ah[mi][3], a1);
                }
            }
#pragma unroll
            for (int jp = 0; jp < 4; ++jp) {
                ldsm4(bh[jp], sb + b_rt[jp] + ((ko + b_koff) ^ b_sw[jp]));
                if (SPL)
                    ldsm4(bl[jp], sb + b_rt[jp] + ((ko + b_koff + 64) ^ b_sw[jp]));
            }
#pragma unroll
            for (int mi = 0; mi < 4; ++mi)
#pragma unroll
                for (int jp = 0; jp < 4; ++jp) {
                    mma16816(acc[mi][2*jp],   ah[mi], bh[jp]);
                    mma16816(acc[mi][2*jp+1], ah[mi], bh[jp] + 2);
                }
            if (SPL) {
#pragma unroll
                for (int mi = 0; mi < 4; ++mi)
#pragma unroll
                    for (int jp = 0; jp < 4; ++jp) {
                        mma16816(acc[mi][2*jp],   ah[mi], bl[jp]);
                        mma16816(acc[mi][2*jp+1], ah[mi], bl[jp] + 2);
                    }
#pragma unroll
                for (int mi = 0; mi < 4; ++mi)
#pragma unroll
                    for (int jp = 0; jp < 4; ++jp) {
                        mma16816(acc[mi][2*jp],   al[mi], bh[jp]);
                        mma16816(acc[mi][2*jp+1], al[mi], bh[jp] + 2);
                    }
            }
        }
        buf = (buf == NSTG - 1) ? 0 : buf + 1;
        nbuf = (nbuf == NSTG - 1) ? 0 : nbuf + 1;
    }

    // -----------------------------------------------------------------------
    // Epilogue
    // -----------------------------------------------------------------------
    const int rbase = bm + warp_m * 64 + (lane >> 2);
    const int cbase = bn + warp_n * 64 + (lane & 3) * 2;

    if (MODE == 1 || MODE == 2) {
        __half* st = (__half*)(smem + STG);   // MODE1 transpose staging
        if (MODE == 1) __syncthreads();
#pragma unroll
        for (int mi = 0; mi < 4; ++mi)
#pragma unroll
            for (int j = 0; j < 8; ++j) {
                const int gc = cbase + j * 8;
#pragma unroll
                for (int half = 0; half < 2; ++half) {
                    const int gr = rbase + mi * 16 + half * 8;
                    float v0 = acc[mi][j][half * 2 + 0];
                    float v1 = acc[mi][j][half * 2 + 1];
                    if (MODE == 1) {
                        const float2 bv = *(const float2*)(bias + gc);
                        v0 += bv.x; v1 += bv.y;
                    }
                    const __half h0 = __float2half(v0);
                    const __half h1 = __float2half(v1);
                    __half2 hp; hp.x = h0; hp.y = h1;
                    __half2 lp;
                    lp.x = __float2half(v0 - __half2float(h0));
                    lp.y = __float2half(v1 - __half2float(h1));
                    *(__half2*)(out_hi + (size_t)gr * DQ + gc) = hp;
                    *(__half2*)(out_lo + (size_t)gr * DQ + gc) = lp;
                    if (MODE == 1) {
                        st[(gc - bn)     * 136 + (gr - bm)] = h0;
                        st[(gc + 1 - bn) * 136 + (gr - bm)] = h1;
                    }
                }
            }
        if (MODE == 1) {
            __syncthreads();
            const int b = bm >> 11, n0 = bm & 2047;
            const __half* src = st + tid * 136;
            __half* dst = out_t + ((size_t)(b * DQ + bn + tid)) * NQ + n0;
#pragma unroll
            for (int k2 = 0; k2 < 16; ++k2)
                *(float4*)(dst + k2 * 8) = *(const float4*)(src + k2 * 8);
        }
    } else if (MODE == 3) {
        // Per-warp 64-col tile stats: mask -> max -> E=__expf(s-m) -> sum.
        // All reductions shfl-only within lane quads; no barriers.
        const int tt = blockIdx.x * 2 + warp_n;   // global 64-tile index 0..31
        // 1) adjacency mask
#pragma unroll
        for (int mi = 0; mi < 4; ++mi)
#pragma unroll
            for (int j = 0; j < 8; ++j)
#pragma unroll
                for (int half = 0; half < 2; ++half) {
                    const int gr = rbase + mi * 16 + half * 8;
                    const int gc = cbase + j * 8;
                    const size_t o = (size_t)z * NQ * NQ + (size_t)gr * NQ + gc;
                    const int2 ad = *(const int2*)(adj + o);
                    if (!ad.x) acc[mi][j][half * 2]     = -1e30f;
                    if (!ad.y) acc[mi][j][half * 2 + 1] = -1e30f;
                }
        // 2) tile max + exp + sum per row (row = quad of lanes)
#pragma unroll
        for (int mi = 0; mi < 4; ++mi)
#pragma unroll
            for (int half = 0; half < 2; ++half) {
                float m = -1e30f;
#pragma unroll
                for (int j = 0; j < 8; ++j)
                    m = fmaxf(m, fmaxf(acc[mi][j][half*2], acc[mi][j][half*2+1]));
                m = fmaxf(m, __shfl_xor_sync(0xffffffffu, m, 1));
                m = fmaxf(m, __shfl_xor_sync(0xffffffffu, m, 2));
                float ssum = 0.f;
#pragma unroll
                for (int j = 0; j < 8; ++j) {
                    const float e0 = __expf(acc[mi][j][half*2]     - m);
                    const float e1 = __expf(acc[mi][j][half*2 + 1] - m);
                    acc[mi][j][half*2]     = e0;
                    acc[mi][j][half*2 + 1] = e1;
                    ssum += e0 + e1;
                }
                ssum += __shfl_xor_sync(0xffffffffu, ssum, 1);
                ssum += __shfl_xor_sync(0xffffffffu, ssum, 2);
                if ((lane & 3) == 0) {
                    const int gr = rbase + mi * 16 + half * 8;
                    const size_t idx = (size_t)tt * MTOT + z * NQ + gr;
                    statm[idx] = m;
                    stats[idx] = ssum;
                }
            }
        // 3) write E (fp16)
#pragma unroll
        for (int mi = 0; mi < 4; ++mi)
#pragma unroll
            for (int j = 0; j < 8; ++j)
#pragma unroll
                for (int half = 0; half < 2; ++half) {
                    const int gr = rbase + mi * 16 + half * 8;
                    const int gc = cbase + j * 8;
                    const size_t o = (size_t)z * NQ * NQ + (size_t)gr * NQ + gc;
                    *(__half2*)(out_hi + o) =
                        __floats2half2_rn(acc[mi][j][half*2], acc[mi][j][half*2+1]);
                }
    } else {
        // MODE 4: elu
#pragma unroll
        for (int mi = 0; mi < 4; ++mi)
#pragma unroll
            for (int j = 0; j < 8; ++j) {
                const int gc = cbase + j * 8;
#pragma unroll
                for (int half = 0; half < 2; ++half) {
                    const int gr = rbase + mi * 16 + half * 8;
                    const float v0 = acc[mi][j][half * 2 + 0];
                    const float v1 = acc[mi][j][half * 2 + 1];
                    const size_t o = (size_t)z * NQ * DQ + (size_t)gr * DQ + gc;
                    float2 ov;
                    ov.x = (v0 > 0.f) ? v0 : expm1f(v0);
                    ov.y = (v1 > 0.f) ? v1 : expm1f(v1);
                    *(float2*)(outf + o) = ov;
                }
            }
    }
}

#define SMEM_G3P (3 * 32768)             // MODE 1/2/3: 98304
#define SMEM_G4  (4 * 16384 + 8192)      // MODE 4: 73728 (stages + alpha)

// ---------------------------------------------------------------------------
// fp32 -> fp16 hi/lo split, vectorized
// ---------------------------------------------------------------------------
__global__ __launch_bounds__(256) void k_split4(
    const float4* __restrict__ in, __half2* __restrict__ hi,
    __half2* __restrict__ lo, int n4)
{
    for (int i = blockIdx.x * 256 + threadIdx.x; i < n4; i += gridDim.x * 256) {
        const float4 v = in[i];
        const __half2 h0 = __floats2half2_rn(v.x, v.y);
        const __half2 h1 = __floats2half2_rn(v.z, v.w);
        const float2 f0 = __half22float2(h0);
        const float2 f1 = __half22float2(h1);
        hi[2*i]   = h0;
        hi[2*i+1] = h1;
        lo[2*i]   = __floats2half2_rn(v.x - f0.x, v.y - f0.y);
        lo[2*i+1] = __floats2half2_rn(v.z - f1.x, v.w - f1.y);
    }
}

// Merged small splits: W (elementwise) and attn (transposed), both DQxDQ.
__global__ __launch_bounds__(256) void k_split_small(
    const float* __restrict__ W, __half* __restrict__ whi, __half* __restrict__ wlo,
    const float* __restrict__ attn, __half* __restrict__ ahi, __half* __restrict__ alo)
{
    for (int i = blockIdx.x * 256 + threadIdx.x; i < DQ * DQ; i += gridDim.x * 256) {
        {
            const float v = W[i];
            const __half h = __float2half(v);
            whi[i] = h;
            wlo[i] = __float2half(v - __half2float(h));
        }
        {
            const int n = i / DQ, k = i % DQ;
            const float v = attn[(size_t)k * DQ + n];
            const __half h = __float2half(v);
            ahi[i] = h;
            alo[i] = __float2half(v - __half2float(h));
        }
    }
}

// ---------------------------------------------------------------------------
// Launch
// ---------------------------------------------------------------------------
extern "C" void kernel_launch(void* const* d_in, const int* in_sizes, int n_in,
                              void* d_out, int out_size)
{
    const float* x    = (const float*)d_in[0];
    const int*   adj  = (const int*)  d_in[1];
    const float* W    = (const float*)d_in[2];
    const float* bias = (const float*)d_in[3];
    const float* attn = (const float*)d_in[4];
    float* out = (float*)d_out;

    __half *x_hi, *x_lo, *w_hi, *w_lo, *at_hi, *at_lo;
    __half *h_hi, *h_lo, *ht_hi, *ha_hi, *ha_lo, *e;
    float *mt, *st;
    cudaGetSymbolAddress((void**)&x_hi,  g_x_hi);  cudaGetSymbolAddress((void**)&x_lo,  g_x_lo);
    cudaGetSymbolAddress((void**)&w_hi,  g_w_hi);  cudaGetSymbolAddress((void**)&w_lo,  g_w_lo);
    cudaGetSymbolAddress((void**)&at_hi, g_at_hi); cudaGetSymbolAddress((void**)&at_lo, g_at_lo);
    cudaGetSymbolAddress((void**)&h_hi,  g_h_hi);  cudaGetSymbolAddress((void**)&h_lo,  g_h_lo);
    cudaGetSymbolAddress((void**)&ht_hi, g_ht_hi);
    cudaGetSymbolAddress((void**)&ha_hi, g_ha_hi); cudaGetSymbolAddress((void**)&ha_lo, g_ha_lo);
    cudaGetSymbolAddress((void**)&e,     g_e);
    cudaGetSymbolAddress((void**)&mt,    g_mt);
    cudaGetSymbolAddress((void**)&st,    g_st);

    cudaFuncSetAttribute(k_mma<1>, cudaFuncAttributeMaxDynamicSharedMemorySize, SMEM_G3P);
    cudaFuncSetAttribute(k_mma<2>, cudaFuncAttributeMaxDynamicSharedMemorySize, SMEM_G3P);
    cudaFuncSetAttribute(k_mma<3>, cudaFuncAttributeMaxDynamicSharedMemorySize, SMEM_G3P);
    cudaFuncSetAttribute(k_mma<4>, cudaFuncAttributeMaxDynamicSharedMemorySize, SMEM_G4);

    // Input splits
    k_split4<<<2048, 256>>>((const float4*)x, (__half2*)x_hi, (__half2*)x_lo,
                            MTOT * DQ / 4);
    k_split_small<<<512, 256>>>(W, w_hi, w_lo, attn, at_hi, at_lo);

    // h = x @ W^T + b  (3-pass), hT_hi produced in epilogue
    k_mma<1><<<dim3(DQ / 128, MTOT / 128, 1), 128, SMEM_G3P>>>(
        x_hi, x_lo, w_hi, w_lo, bias, nullptr, nullptr, h_hi, h_lo, ht_hi,
        nullptr, nullptr);

    // ha = h @ attn  (3-pass)
    k_mma<2><<<dim3(DQ / 128, MTOT / 128, 1), 128, SMEM_G3P>>>(
        h_hi, h_lo, at_hi, at_lo, nullptr, nullptr, nullptr, ha_hi, ha_lo, nullptr,
        nullptr, nullptr);

    // scores -> masked exp tiles: E fp16 + (m_t, S_t)  (fused softmax part 1)
    k_mma<3><<<dim3(NQ / 128, NQ / 128, BQ), 128, SMEM_G3P>>>(
        ha_hi, ha_lo, h_hi, h_lo, nullptr, adj, nullptr, e, nullptr, nullptr,
        mt, st);

    // out = elu( sum_t alpha_t E_t @ h ) per batch  (fused softmax part 2)
    k_mma<4><<<dim3(DQ / 128, NQ / 128, BQ), 128, SMEM_G4>>>(
        e, e, ht_hi, ht_hi, nullptr, nullptr, out, nullptr, nullptr, nullptr,
        mt, st);
}

// round 16
// speedup vs baseline: 1.2060x; 1.0444x over previous
#include <cuda_runtime.h>
#include <cuda_fp16.h>
#include <cstdint>
#include <math.h>

// ---------------------------------------------------------------------------
// Problem constants
// ---------------------------------------------------------------------------
#define BQ 8
#define NQ 2048
#define DQ 512
#define MTOT (BQ * NQ)   // 16384
#define NTILE 32         // score col-tiles per row (2048/64), one per warp_n

// ---------------------------------------------------------------------------
// Device scratch (no runtime allocation allowed)
// ---------------------------------------------------------------------------
__device__ __half g_x_hi[MTOT * DQ], g_x_lo[MTOT * DQ];
__device__ __half g_w_hi[DQ * DQ],   g_w_lo[DQ * DQ];
__device__ __half g_at_hi[DQ * DQ],  g_at_lo[DQ * DQ];     // attn^T
__device__ __half g_h_hi[MTOT * DQ],  g_h_lo[MTOT * DQ];
__device__ __half g_ht_hi[MTOT * DQ];                      // per-batch H^T (hi only)
__device__ __half g_ha_hi[MTOT * DQ], g_ha_lo[MTOT * DQ];
__device__ __half g_e[(size_t)BQ * NQ * NQ];               // E = exp(s - m_t), fp16
__device__ float g_mt[(size_t)NTILE * MTOT];               // [tile][row] max
__device__ float g_st[(size_t)NTILE * MTOT];               // [tile][row] sum

// ---------------------------------------------------------------------------
// Low-level helpers (base compute_103 features only)
// ---------------------------------------------------------------------------
__device__ __forceinline__ uint32_t smem_u32(const void* p) {
    uint32_t a;
    asm("{ .reg .u64 t; cvta.to.shared.u64 t, %1; cvt.u32.u64 %0, t; }" : "=r"(a) : "l"(p));
    return a;
}

#define CP16(dst, src) \
    asm volatile("cp.async.cg.shared.global [%0], [%1], 16;\n" :: "r"(dst), "l"(src) : "memory")
#define CP_COMMIT() asm volatile("cp.async.commit_group;\n" ::: "memory")
#define CP_WAIT1()  asm volatile("cp.async.wait_group 1;\n" ::: "memory")
#define CP_WAIT2()  asm volatile("cp.async.wait_group 2;\n" ::: "memory")

__device__ __forceinline__ void ldsm4(uint32_t* r, uint32_t addr) {
    asm volatile("ldmatrix.sync.aligned.m8n8.x4.shared.b16 {%0,%1,%2,%3}, [%4];\n"
                 : "=r"(r[0]), "=r"(r[1]), "=r"(r[2]), "=r"(r[3]) : "r"(addr));
}

__device__ __forceinline__ void mma16816(float* c, const uint32_t* a, const uint32_t* b) {
    asm volatile(
        "mma.sync.aligned.m16n8k16.row.col.f32.f16.f16.f32 "
        "{%0,%1,%2,%3}, {%4,%5,%6,%7}, {%8,%9}, {%0,%1,%2,%3};\n"
        : "+f"(c[0]), "+f"(c[1]), "+f"(c[2]), "+f"(c[3])
        : "r"(a[0]), "r"(a[1]), "r"(a[2]), "r"(a[3]), "r"(b[0]), "r"(b[1]));
}

__device__ __forceinline__ uint32_t mulh2(uint32_t x, __half2 a) {
    __half2 v = *(__half2*)&x;
    v = __hmul2(v, a);
    return *(uint32_t*)&v;
}

// ---------------------------------------------------------------------------
// Unified HMMA GEMM: C[m,n] = sum_k A[m,k] * B[n,k] via fp16 split
// CTA tile 128x128, 128 threads = 4 warps (2M x 2N), warp 64x64, fp32 acc,
// pass-major inner loop.
// MODES 1-3: 3-pass (hh+hl+lh), 3-stage pipeline.
// MODE 4:    1-pass, 4-stage pipeline, A-fragments scaled per-(row,64-tile)
//            by alpha = exp(m_t - M)/L computed in-kernel from (m_t, S_t).
// MODE 1: out = C + bias -> h hi/lo + fused hT_hi   (M=16384,N=512,K=512)
// MODE 2: out = C        -> ha hi/lo                 (M=16384,N=512,K=512)
// MODE 3: masked exp, per-(row, warp_n 64-col tile) max: E fp16 + m_t + S_t
//         (all reductions shfl-only, zero epilogue barriers)
// MODE 4: out = elu( sum_t alpha_t * E_t @ h_t ) -> fp32
// ---------------------------------------------------------------------------
template <int MODE>
__global__ __launch_bounds__(128, 2) void k_mma(
    const __half* __restrict__ Ahi, const __half* __restrict__ Alo,
    const __half* __restrict__ Bhi, const __half* __restrict__ Blo,
    const float* __restrict__ bias, const int* __restrict__ adj,
    float* __restrict__ outf,
    __half* __restrict__ out_hi, __half* __restrict__ out_lo,
    __half* __restrict__ out_t,
    float* __restrict__ statm, float* __restrict__ stats)
{
    constexpr bool SPL  = (MODE != 4);
    constexpr int KDIM = (MODE == 4) ? 2048 : 512;
    constexpr int LDA  = (MODE == 4) ? 2048 : 512;
    constexpr int LDB  = (MODE == 4) ? 2048 : 512;
    constexpr int NST  = KDIM / 32;
    constexpr int ASB  = SPL ? 16384 : 8192;
    constexpr int BSB  = SPL ? 16384 : 8192;
    constexpr int STG  = ASB + BSB;
    constexpr int NSTG = SPL ? 3 : 4;

    extern __shared__ char smem[];
    const uint32_t sbase = smem_u32(smem);
    const int tid = threadIdx.x;
    const int lane = tid & 31, wid = tid >> 5;
    const int warp_m = wid & 1;
    const int warp_n = wid >> 1;

    const int bn = blockIdx.x * 128, bm = blockIdx.y * 128, z = blockIdx.z;
    size_t aoff = 0, boff = 0;
    if (MODE == 3) { aoff = (size_t)z * NQ * DQ; boff = (size_t)z * NQ * DQ; }
    if (MODE == 4) { aoff = (size_t)z * NQ * NQ; boff = (size_t)z * DQ * NQ; }

    const char* A0h = (const char*)(Ahi + aoff + (size_t)bm * LDA);
    const char* A0l = (const char*)(Alo + aoff + (size_t)bm * LDA);
    const char* B0h = (const char*)(Bhi + boff + (size_t)bn * LDB);
    const char* B0l = (const char*)(Blo + boff + (size_t)bn * LDB);

    auto issue_stage = [&](uint32_t sd, int kb) {
        if (SPL) {
            const uint32_t row0 = tid >> 3;
            const uint32_t c = tid & 7;
            const uint32_t off = c * 16;
            const char* srcA = (c < 4) ? A0h : A0l;
            const char* srcB = (c < 4) ? B0h : B0l;
            const int cb = (c & 3) * 16;
#pragma unroll
            for (int blk = 0; blk < 8; ++blk) {
                const uint32_t row = row0 + blk * 16;
                const uint32_t sw = row * 128 + (off ^ ((row & 7) << 4));
                CP16(sd + sw,       srcA + (size_t)row * (LDA * 2) + kb + cb);
                CP16(sd + ASB + sw, srcB + (size_t)row * (LDB * 2) + kb + cb);
            }
        } else {
            const uint32_t row0 = tid >> 2;
            const uint32_t c = tid & 3;
            const uint32_t off = c * 16;
#pragma unroll
            for (int blk = 0; blk < 4; ++blk) {
                const uint32_t row = row0 + blk * 32;
                const uint32_t sw = row * 64 + (off ^ ((row & 3) << 4));
                CP16(sd + sw,       A0h + (size_t)row * (LDA * 2) + kb + c * 16);
                CP16(sd + ASB + sw, B0h + (size_t)row * (LDB * 2) + kb + c * 16);
            }
        }
    };

    // Prologue FIRST so the stat loads / exp chain (MODE 4) overlap the fetch.
#pragma unroll
    for (int sgi = 0; sgi < NSTG - 1; ++sgi) {
        issue_stage(sbase + sgi * STG, sgi * 64);
        CP_COMMIT();
    }

    // MODE 4: per-(row, 64-tile) alpha into smem (placed after the 4 stages).
    // stats layout [tile][row] -> coalesced loads. First mainloop
    // __syncthreads orders these writes before any cross-thread read.
    __half* s_alpha = (__half*)(smem + 4 * 16384);   // [NTILE][128] half
    if (MODE == 4) {
        const int rowbase = z * NQ + bm + tid;
        float M = -1e30f;
#pragma unroll
        for (int t = 0; t < NTILE; ++t)
            M = fmaxf(M, statm[(size_t)t * MTOT + rowbase]);
        float L = 0.f;
#pragma unroll
        for (int t = 0; t < NTILE; ++t)
            L += __expf(statm[(size_t)t * MTOT + rowbase] - M) *
                 stats[(size_t)t * MTOT + rowbase];
        const float invL = 1.f / L;
#pragma unroll
        for (int t = 0; t < NTILE; ++t)
            s_alpha[t * 128 + tid] =
                __float2half(__expf(statm[(size_t)t * MTOT + rowbase] - M) * invL);
    }

    uint32_t a_rt[4], a_sw[4];
#pragma unroll
    for (int mi = 0; mi < 4; ++mi) {
        const uint32_t r = warp_m * 64 + mi * 16 + (lane & 15);
        if (SPL) { a_rt[mi] = r * 128; a_sw[mi] = (r & 7) << 4; }
        else     { a_rt[mi] = r * 64;  a_sw[mi] = (r & 3) << 4; }
    }
    uint32_t b_rt[4], b_sw[4];
    {
        const uint32_t brow = (lane & 7) + ((lane >> 4) & 1) * 8;
#pragma unroll
        for (int jp = 0; jp < 4; ++jp) {
            const uint32_t r = warp_n * 64 + jp * 16 + brow;
            if (SPL) { b_rt[jp] = r * 128; b_sw[jp] = (r & 7) << 4; }
            else     { b_rt[jp] = r * 64;  b_sw[jp] = (r & 3) << 4; }
        }
    }
    const uint32_t a_koff = (lane >> 4) * 16;
    const uint32_t b_koff = ((lane >> 3) & 1) * 16;

    float acc[4][8][4];
#pragma unroll
    for (int i = 0; i < 4; ++i)
#pragma unroll
        for (int j = 0; j < 8; ++j)
#pragma unroll
            for (int k = 0; k < 4; ++k) acc[i][j][k] = 0.f;

    int buf = 0, nbuf = NSTG - 1;
    for (int i = 0; i < NST; ++i) {
        if (SPL) { CP_WAIT1(); } else { CP_WAIT2(); }
        __syncthreads();
        if (i + NSTG - 1 < NST)
            issue_stage(sbase + nbuf * STG, (i + NSTG - 1) * 64);
        CP_COMMIT();

        const uint32_t sa = sbase + buf * STG;
        const uint32_t sb = sa + ASB;
#pragma unroll
        for (int ks = 0; ks < 2; ++ks) {
            const uint32_t ko = ks * 32;
            uint32_t ah[4][4], al[4][4], bh[4][4], bl[4][4];
#pragma unroll
            for (int mi = 0; mi < 4; ++mi) {
                ldsm4(ah[mi], sa + a_rt[mi] + ((ko + a_koff) ^ a_sw[mi]));
                if (SPL)
                    ldsm4(al[mi], sa + a_rt[mi] + ((ko + a_koff + 64) ^ a_sw[mi]));
            }
            if (!SPL) {
                // scale A fragments (rows of E) by alpha[row][64-tile]
                const int tt = i >> 1;
#pragma unroll
                for (int mi = 0; mi < 4; ++mi) {
                    const int r0 = warp_m * 64 + mi * 16 + (lane >> 2);
                    const __half2 a0 = __half2half2(s_alpha[tt * 128 + r0]);
                    const __half2 a1 = __half2half2(s_alpha[tt * 128 + r0 + 8]);
                    ah[mi][0] = mulh2(ah[mi][0], a0);
                    ah[mi][2] = mulh2(ah[mi][2], a0);
                    ah[mi][1] = mulh2(ah[mi][1], a1);
                    ah[mi][3] = mulh2(ah[mi][3], a1);
                }
            }
#pragma unroll
            for (int jp = 0; jp < 4; ++jp) {
                ldsm4(bh[jp], sb + b_rt[jp] + ((ko + b_koff) ^ b_sw[jp]));
                if (SPL)
                    ldsm4(bl[jp], sb + b_rt[jp] + ((ko + b_koff + 64) ^ b_sw[jp]));
            }
#pragma unroll
            for (int mi = 0; mi < 4; ++mi)
#pragma unroll
                for (int jp = 0; jp < 4; ++jp) {
                    mma16816(acc[mi][2*jp],   ah[mi], bh[jp]);
                    mma16816(acc[mi][2*jp+1], ah[mi], bh[jp] + 2);
                }
            if (SPL) {
#pragma unroll
                for (int mi = 0; mi < 4; ++mi)
#pragma unroll
                    for (int jp = 0; jp < 4; ++jp) {
                        mma16816(acc[mi][2*jp],   ah[mi], bl[jp]);
                        mma16816(acc[mi][2*jp+1], ah[mi], bl[jp] + 2);
                    }
#pragma unroll
                for (int mi = 0; mi < 4; ++mi)
#pragma unroll
                    for (int jp = 0; jp < 4; ++jp) {
                        mma16816(acc[mi][2*jp],   al[mi], bh[jp]);
                        mma16816(acc[mi][2*jp+1], al[mi], bh[jp] + 2);
                    }
            }
        }
        buf = (buf == NSTG - 1) ? 0 : buf + 1;
        nbuf = (nbuf == NSTG - 1) ? 0 : nbuf + 1;
    }

    // -----------------------------------------------------------------------
    // Epilogue
    // -----------------------------------------------------------------------
    const int rbase = bm + warp_m * 64 + (lane >> 2);
    const int cbase = bn + warp_n * 64 + (lane & 3) * 2;

    if (MODE == 1 || MODE == 2) {
        __half* st = (__half*)(smem + STG);   // MODE1 transpose staging
        if (MODE == 1) __syncthreads();
#pragma unroll
        for (int mi = 0; mi < 4; ++mi)
#pragma unroll
            for (int j = 0; j < 8; ++j) {
                const int gc = cbase + j * 8;
#pragma unroll
                for (int half = 0; half < 2; ++half) {
                    const int gr = rbase + mi * 16 + half * 8;
                    float v0 = acc[mi][j][half * 2 + 0];
                    float v1 = acc[mi][j][half * 2 + 1];
                    if (MODE == 1) {
                        const float2 bv = *(const float2*)(bias + gc);
                        v0 += bv.x; v1 += bv.y;
                    }
                    const __half h0 = __float2half(v0);
                    const __half h1 = __float2half(v1);
                    __half2 hp; hp.x = h0; hp.y = h1;
                    __half2 lp;
                    lp.x = __float2half(v0 - __half2float(h0));
                    lp.y = __float2half(v1 - __half2float(h1));
                    *(__half2*)(out_hi + (size_t)gr * DQ + gc) = hp;
                    *(__half2*)(out_lo + (size_t)gr * DQ + gc) = lp;
                    if (MODE == 1) {
                        st[(gc - bn)     * 136 + (gr - bm)] = h0;
                        st[(gc + 1 - bn) * 136 + (gr - bm)] = h1;
                    }
                }
            }
        if (MODE == 1) {
            __syncthreads();
            const int b = bm >> 11, n0 = bm & 2047;
            const __half* src = st + tid * 136;
            __half* dst = out_t + ((size_t)(b * DQ + bn + tid)) * NQ + n0;
#pragma unroll
            for (int k2 = 0; k2 < 16; ++k2)
                *(float4*)(dst + k2 * 8) = *(const float4*)(src + k2 * 8);
        }
    } else if (MODE == 3) {
        // Per-warp 64-col tile stats: mask -> max -> E=__expf(s-m) -> sum.
        const int tt = blockIdx.x * 2 + warp_n;   // global 64-tile index 0..31
#pragma unroll
        for (int mi = 0; mi < 4; ++mi)
#pragma unroll
            for (int j = 0; j < 8; ++j)
#pragma unroll
                for (int half = 0; half < 2; ++half) {
                    const int gr = rbase + mi * 16 + half * 8;
                    const int gc = cbase + j * 8;
                    const size_t o = (size_t)z * NQ * NQ + (size_t)gr * NQ + gc;
                    const int2 ad = *(const int2*)(adj + o);
                    if (!ad.x) acc[mi][j][half * 2]     = -1e30f;
                    if (!ad.y) acc[mi][j][half * 2 + 1] = -1e30f;
                }
#pragma unroll
        for (int mi = 0; mi < 4; ++mi)
#pragma unroll
            for (int half = 0; half < 2; ++half) {
                float m = -1e30f;
#pragma unroll
                for (int j = 0; j < 8; ++j)
                    m = fmaxf(m, fmaxf(acc[mi][j][half*2], acc[mi][j][half*2+1]));
                m = fmaxf(m, __shfl_xor_sync(0xffffffffu, m, 1));
                m = fmaxf(m, __shfl_xor_sync(0xffffffffu, m, 2));
                float ssum = 0.f;
#pragma unroll
                for (int j = 0; j < 8; ++j) {
                    const float e0 = __expf(acc[mi][j][half*2]     - m);
                    const float e1 = __expf(acc[mi][j][half*2 + 1] - m);
                    acc[mi][j][half*2]     = e0;
                    acc[mi][j][half*2 + 1] = e1;
                    ssum += e0 + e1;
                }
                ssum += __shfl_xor_sync(0xffffffffu, ssum, 1);
                ssum += __shfl_xor_sync(0xffffffffu, ssum, 2);
                if ((lane & 3) == 0) {
                    const int gr = rbase + mi * 16 + half * 8;
                    const size_t idx = (size_t)tt * MTOT + z * NQ + gr;
                    statm[idx] = m;
                    stats[idx] = ssum;
                }
            }
#pragma unroll
        for (int mi = 0; mi < 4; ++mi)
#pragma unroll
            for (int j = 0; j < 8; ++j)
#pragma unroll
                for (int half = 0; half < 2; ++half) {
                    const int gr = rbase + mi * 16 + half * 8;
                    const int gc = cbase + j * 8;
                    const size_t o = (size_t)z * NQ * NQ + (size_t)gr * NQ + gc;
                    *(__half2*)(out_hi + o) =
                        __floats2half2_rn(acc[mi][j][half*2], acc[mi][j][half*2+1]);
                }
    } else {
        // MODE 4: elu via fast exp (abs err ~2^-21: negligible)
#pragma unroll
        for (int mi = 0; mi < 4; ++mi)
#pragma unroll
            for (int j = 0; j < 8; ++j) {
                const int gc = cbase + j * 8;
#pragma unroll
                for (int half = 0; half < 2; ++half) {
                    const int gr = rbase + mi * 16 + half * 8;
                    const float v0 = acc[mi][j][half * 2 + 0];
                    const float v1 = acc[mi][j][half * 2 + 1];
                    const size_t o = (size_t)z * NQ * DQ + (size_t)gr * DQ + gc;
                    float2 ov;
                    ov.x = (v0 > 0.f) ? v0 : (__expf(v0) - 1.f);
                    ov.y = (v1 > 0.f) ? v1 : (__expf(v1) - 1.f);
                    *(float2*)(outf + o) = ov;
                }
            }
    }
}

#define SMEM_G3P (3 * 32768)             // MODE 1/2/3: 98304
#define SMEM_G4  (4 * 16384 + 8192)      // MODE 4: 73728 (stages + alpha)

// ---------------------------------------------------------------------------
// Merged split kernel: x (vectorized float4) + W (elementwise) + attn^T.
// ---------------------------------------------------------------------------
__global__ __launch_bounds__(256) void k_split_all(
    const float4* __restrict__ x4, __half2* __restrict__ xhi2,
    __half2* __restrict__ xlo2,
    const float* __restrict__ W, __half* __restrict__ whi, __half* __restrict__ wlo,
    const float* __restrict__ attn, __half* __restrict__ ahi, __half* __restrict__ alo)
{
    const int gt = blockIdx.x * 256 + threadIdx.x;
    const int nthr = gridDim.x * 256;
    // x: MTOT*DQ/4 float4 elements
    for (int i = gt; i < MTOT * DQ / 4; i += nthr) {
        const float4 v = x4[i];
        const __half2 h0 = __floats2half2_rn(v.x, v.y);
        const __half2 h1 = __floats2half2_rn(v.z, v.w);
        const float2 f0 = __half22float2(h0);
        const float2 f1 = __half22float2(h1);
        xhi2[2*i]   = h0;
        xhi2[2*i+1] = h1;
        xlo2[2*i]   = __floats2half2_rn(v.x - f0.x, v.y - f0.y);
        xlo2[2*i+1] = __floats2half2_rn(v.z - f1.x, v.w - f1.y);
    }
    // W + attn^T: DQ*DQ scalars each
    for (int i = gt; i < DQ * DQ; i += nthr) {
        {
            const float v = W[i];
            const __half h = __float2half(v);
            whi[i] = h;
            wlo[i] = __float2half(v - __half2float(h));
        }
        {
            const int n = i / DQ, k = i % DQ;
            const float v = attn[(size_t)k * DQ + n];
            const __half h = __float2half(v);
            ahi[i] = h;
            alo[i] = __float2half(v - __half2float(h));
        }
    }
}

// ---------------------------------------------------------------------------
// Launch
// ---------------------------------------------------------------------------
extern "C" void kernel_launch(void* const* d_in, const int* in_sizes, int n_in,
                              void* d_out, int out_size)
{
    const float* x    = (const float*)d_in[0];
    const int*   adj  = (const int*)  d_in[1];
    const float* W    = (const float*)d_in[2];
    const float* bias = (const float*)d_in[3];
    const float* attn = (const float*)d_in[4];
    float* out = (float*)d_out;

    __half *x_hi, *x_lo, *w_hi, *w_lo, *at_hi, *at_lo;
    __half *h_hi, *h_lo, *ht_hi, *ha_hi, *ha_lo, *e;
    float *mt, *st;
    cudaGetSymbolAddress((void**)&x_hi,  g_x_hi);  cudaGetSymbolAddress((void**)&x_lo,  g_x_lo);
    cudaGetSymbolAddress((void**)&w_hi,  g_w_hi);  cudaGetSymbolAddress((void**)&w_lo,  g_w_lo);
    cudaGetSymbolAddress((void**)&at_hi, g_at_hi); cudaGetSymbolAddress((void**)&at_lo, g_at_lo);
    cudaGetSymbolAddress((void**)&h_hi,  g_h_hi);  cudaGetSymbolAddress((void**)&h_lo,  g_h_lo);
    cudaGetSymbolAddress((void**)&ht_hi, g_ht_hi);
    cudaGetSymbolAddress((void**)&ha_hi, g_ha_hi); cudaGetSymbolAddress((void**)&ha_lo, g_ha_lo);
    cudaGetSymbolAddress((void**)&e,     g_e);
    cudaGetSymbolAddress((void**)&mt,    g_mt);
    cudaGetSymbolAddress((void**)&st,    g_st);

    cudaFuncSetAttribute(k_mma<1>, cudaFuncAttributeMaxDynamicSharedMemorySize, SMEM_G3P);
    cudaFuncSetAttribute(k_mma<2>, cudaFuncAttributeMaxDynamicSharedMemorySize, SMEM_G3P);
    cudaFuncSetAttribute(k_mma<3>, cudaFuncAttributeMaxDynamicSharedMemorySize, SMEM_G3P);
    cudaFuncSetAttribute(k_mma<4>, cudaFuncAttributeMaxDynamicSharedMemorySize, SMEM_G4);

    // Input splits (single launch: x + W + attn^T)
    k_split_all<<<2048, 256>>>((const float4*)x, (__half2*)x_hi, (__half2*)x_lo,
                               W, w_hi, w_lo, attn, at_hi, at_lo);

    // h = x @ W^T + b  (3-pass), hT_hi produced in epilogue
    k_mma<1><<<dim3(DQ / 128, MTOT / 128, 1), 128, SMEM_G3P>>>(
        x_hi, x_lo, w_hi, w_lo, bias, nullptr, nullptr, h_hi, h_lo, ht_hi,
        nullptr, nullptr);

    // ha = h @ attn  (3-pass)
    k_mma<2><<<dim3(DQ / 128, MTOT / 128, 1), 128, SMEM_G3P>>>(
        h_hi, h_lo, at_hi, at_lo, nullptr, nullptr, nullptr, ha_hi, ha_lo, nullptr,
        nullptr, nullptr);

    // scores -> masked exp tiles: E fp16 + (m_t, S_t)  (fused softmax part 1)
    k_mma<3><<<dim3(NQ / 128, NQ / 128, BQ), 128, SMEM_G3P>>>(
        ha_hi, ha_lo, h_hi, h_lo, nullptr, adj, nullptr, e, nullptr, nullptr,
        mt, st);

    // out = elu( sum_t alpha_t E_t @ h ) per batch  (fused softmax part 2)
    k_mma<4><<<dim3(DQ / 128, NQ / 128, BQ), 128, SMEM_G4>>>(
        e, e, ht_hi, ht_hi, nullptr, nullptr, out, nullptr, nullptr, nullptr,
        mt, st);
}

// round 17
// speedup vs baseline: 1.2921x; 1.0715x over previous
#include <cuda_runtime.h>
#include <cuda_fp16.h>
#include <cstdint>
#include <math.h>

// ---------------------------------------------------------------------------
// Problem constants
// ---------------------------------------------------------------------------
#define BQ 8
#define NQ 2048
#define DQ 512
#define MTOT (BQ * NQ)   // 16384
#define NTILE 32         // score col-tiles per row (2048/64), one per warp_n

// ---------------------------------------------------------------------------
// Tiled operand layouts (global memory):
//  T3 (split hi|lo): tile = 128 rows x 32 k = 16384 B; row = 128 B
//      [hi 64B | lo 64B], phys = row*128 + (off ^ ((row&7)<<4)).
//  T1 (fp16 only):   tile = 128 rows x 32 k = 8192 B; row = 64 B,
//      phys = row*64 + (off ^ ((row&3)<<4)).
//  Buffer = [row_block][k_chunk] of tiles -> each GEMM stage is ONE
//  contiguous tile per operand, fetched with a single cp.async.bulk.
// ---------------------------------------------------------------------------
__device__ char g_x_t [(size_t)(MTOT/128) * 16 * 16384];   // 32 MiB
__device__ char g_w_t [(size_t)4  * 16 * 16384];           // 1 MiB
__device__ char g_at_t[(size_t)4  * 16 * 16384];           // 1 MiB (attn^T)
__device__ char g_h_t [(size_t)(MTOT/128) * 16 * 16384];   // 32 MiB
__device__ char g_ha_t[(size_t)(MTOT/128) * 16 * 16384];   // 32 MiB
__device__ char g_e_t [(size_t)(MTOT/128) * 64 * 8192];    // 64 MiB (E fp16)
__device__ char g_ht_t[(size_t)32 * 64 * 8192];            // 16 MiB (hT fp16)
__device__ float g_mt[(size_t)NTILE * MTOT];               // [tile][row] max
__device__ float g_st[(size_t)NTILE * MTOT];               // [tile][row] sum

// ---------------------------------------------------------------------------
// Low-level helpers (base compute_103 / sm_90 features only)
// ---------------------------------------------------------------------------
__device__ __forceinline__ uint32_t smem_u32(const void* p) {
    uint32_t a;
    asm("{ .reg .u64 t; cvta.to.shared.u64 t, %1; cvt.u32.u64 %0, t; }" : "=r"(a) : "l"(p));
    return a;
}

#define MBAR_INIT(m, c) \
    asm volatile("mbarrier.init.shared.b64 [%0], %1;" :: "r"(m), "r"((uint32_t)(c)) : "memory")
#define MBAR_EXPECT(m, b) \
    asm volatile("mbarrier.arrive.expect_tx.shared.b64 _, [%0], %1;" :: "r"(m), "r"((uint32_t)(b)) : "memory")
#define CP_BULK(dst, src, bytes, mbar) \
    asm volatile("cp.async.bulk.shared::cluster.global.mbarrier::complete_tx::bytes [%0], [%1], %2, [%3];" \
                 :: "r"(dst), "l"(src), "r"((uint32_t)(bytes)), "r"(mbar) : "memory")

#define MBAR_WAIT(mbar_addr, phase_parity) do { \
    uint32_t _mbar = (uint32_t)(mbar_addr); \
    uint32_t _parity = (uint32_t)(phase_parity); \
    uint32_t _done; \
    asm volatile("{\n\t.reg .pred p;\n\t" \
        "mbarrier.try_wait.parity.acquire.cta.shared::cta.b64 p, [%1], %2;\n\t" \
        "selp.b32 %0, 1, 0, p;\n\t}" \
        : "=r"(_done) : "r"(_mbar), "r"(_parity) : "memory"); \
    if (!_done) { \
        asm volatile("{\n\t.reg .pred P1;\n\t" \
            "WAIT_LOOP_%=:\n\t" \
            "mbarrier.try_wait.parity.acquire.cta.shared::cta.b64 P1, [%0], %1, 0x989680;\n\t" \
            "@P1 bra.uni WAIT_DONE_%=;\n\t" \
            "bra.uni WAIT_LOOP_%=;\n\t" \
            "WAIT_DONE_%=:\n\t}" \
            :: "r"(_mbar), "r"(_parity) : "memory"); \
    } \
} while (0)

__device__ __forceinline__ void ldsm4(uint32_t* r, uint32_t addr) {
    asm volatile("ldmatrix.sync.aligned.m8n8.x4.shared.b16 {%0,%1,%2,%3}, [%4];\n"
                 : "=r"(r[0]), "=r"(r[1]), "=r"(r[2]), "=r"(r[3]) : "r"(addr));
}

__device__ __forceinline__ void mma16816(float* c, const uint32_t* a, const uint32_t* b) {
    asm volatile(
        "mma.sync.aligned.m16n8k16.row.col.f32.f16.f16.f32 "
        "{%0,%1,%2,%3}, {%4,%5,%6,%7}, {%8,%9}, {%0,%1,%2,%3};\n"
        : "+f"(c[0]), "+f"(c[1]), "+f"(c[2]), "+f"(c[3])
        : "r"(a[0]), "r"(a[1]), "r"(a[2]), "r"(a[3]), "r"(b[0]), "r"(b[1]));
}

__device__ __forceinline__ uint32_t mulh2(uint32_t x, __half2 a) {
    __half2 v = *(__half2*)&x;
    v = __hmul2(v, a);
    return *(uint32_t*)&v;
}

// ---------------------------------------------------------------------------
// Unified HMMA GEMM over tiled operands; stage fetch = 2x cp.async.bulk.
// CTA tile 128x128, 128 threads = 4 warps (2M x 2N), warp 64x64, fp32 acc,
// pass-major inner loop (bit-identical numerics to R16).
// MODE 1: h = x@W^T + b -> h_t (T3) + ht_t (T1)     (M=16384, K=512)
// MODE 2: ha = h@attn   -> ha_t (T3)                 (M=16384, K=512)
// MODE 3: masked exp tiles -> e_t (T1) + (m_t, S_t)  (per batch, K=512)
// MODE 4: out = elu( sum_t alpha_t E_t @ hT ) -> fp32 (per batch, K=2048)
// ---------------------------------------------------------------------------
template <int MODE>
__global__ __launch_bounds__(128, 2) void k_mma(
    const char* __restrict__ At, const char* __restrict__ Bt,
    const float* __restrict__ bias, const int* __restrict__ adj,
    float* __restrict__ outf, char* __restrict__ outT3, char* __restrict__ outT1,
    float* __restrict__ statm, float* __restrict__ stats)
{
    constexpr bool SPL  = (MODE != 4);
    constexpr int KDIM = (MODE == 4) ? 2048 : 512;
    constexpr int NST  = KDIM / 32;          // chunks = stages of work
    constexpr int TSZ  = SPL ? 16384 : 8192; // per-operand tile bytes
    constexpr int STG  = 2 * TSZ;            // stage bytes (A + B)
    constexpr int NSTG = SPL ? 3 : 4;        // pipeline depth
    constexpr int MBOFF = NSTG * STG;        // mbar smem offset

    extern __shared__ char smem[];
    const uint32_t sbase = smem_u32(smem);
    const uint32_t mbase = sbase + MBOFF;
    const int tid = threadIdx.x;
    const int lane = tid & 31, wid = tid >> 5;
    const int warp_m = wid & 1;
    const int warp_n = wid >> 1;

    const int bn = blockIdx.x * 128, bm = blockIdx.y * 128, z = blockIdx.z;

    // Tile-sequence base pointers: [row_block][chunk] of TSZ tiles.
    int a_rb, b_rb;
    if (MODE == 1 || MODE == 2) { a_rb = bm >> 7;            b_rb = bn >> 7; }
    else if (MODE == 3)         { a_rb = (z * NQ + bm) >> 7; b_rb = (z * NQ + bn) >> 7; }
    else                        { a_rb = (z * NQ + bm) >> 7; b_rb = (z * DQ + bn) >> 7; }
    const char* Asrc = At + (size_t)a_rb * NST * TSZ;
    const char* Bsrc = Bt + (size_t)b_rb * NST * TSZ;

    // mbarrier init
    if (tid == 0) {
#pragma unroll
        for (int s = 0; s < NSTG; ++s) MBAR_INIT(mbase + s * 8, 1);
    }
    __syncthreads();

    auto issue = [&](int slot, int chunk) {
        if (tid == 0) {
            const uint32_t mb = mbase + slot * 8;
            MBAR_EXPECT(mb, 2 * TSZ);
            CP_BULK(sbase + slot * STG,       Asrc + (size_t)chunk * TSZ, TSZ, mb);
            CP_BULK(sbase + slot * STG + TSZ, Bsrc + (size_t)chunk * TSZ, TSZ, mb);
        }
    };

    // prologue
#pragma unroll
    for (int s = 0; s < NSTG - 1; ++s) issue(s, s);

    // MODE 4: per-(row, 64-tile) alpha into smem (after the 4 stages);
    // overlaps the prologue bulk copies. stats layout [tile][row].
    __half* s_alpha = (__half*)(smem + 4 * 8192 * 2);   // 65536 (MODE 4 only)
    if (MODE == 4) {
        const int rowbase = z * NQ + bm + tid;
        float M = -1e30f;
#pragma unroll
        for (int t = 0; t < NTILE; ++t)
            M = fmaxf(M, statm[(size_t)t * MTOT + rowbase]);
        float L = 0.f;
#pragma unroll
        for (int t = 0; t < NTILE; ++t)
            L += __expf(statm[(size_t)t * MTOT + rowbase] - M) *
                 stats[(size_t)t * MTOT + rowbase];
        const float invL = 1.f / L;
#pragma unroll
        for (int t = 0; t < NTILE; ++t)
            s_alpha[t * 128 + tid] =
                __float2half(__expf(statm[(size_t)t * MTOT + rowbase] - M) * invL);
    }

    // ldmatrix per-lane bases (same in-smem tile formats as before)
    uint32_t a_rt[4], a_sw[4];
#pragma unroll
    for (int mi = 0; mi < 4; ++mi) {
        const uint32_t r = warp_m * 64 + mi * 16 + (lane & 15);
        if (SPL) { a_rt[mi] = r * 128; a_sw[mi] = (r & 7) << 4; }
        else     { a_rt[mi] = r * 64;  a_sw[mi] = (r & 3) << 4; }
    }
    uint32_t b_rt[4], b_sw[4];
    {
        const uint32_t brow = (lane & 7) + ((lane >> 4) & 1) * 8;
#pragma unroll
        for (int jp = 0; jp < 4; ++jp) {
            const uint32_t r = warp_n * 64 + jp * 16 + brow;
            if (SPL) { b_rt[jp] = r * 128; b_sw[jp] = (r & 7) << 4; }
            else     { b_rt[jp] = r * 64;  b_sw[jp] = (r & 3) << 4; }
        }
    }
    const uint32_t a_koff = (lane >> 4) * 16;
    const uint32_t b_koff = ((lane >> 3) & 1) * 16;

    float acc[4][8][4];
#pragma unroll
    for (int i = 0; i < 4; ++i)
#pragma unroll
        for (int j = 0; j < 8; ++j)
#pragma unroll
            for (int k = 0; k < 4; ++k) acc[i][j][k] = 0.f;

    uint32_t ph = 0;
    int buf = 0, nbuf = NSTG - 1;
    for (int i = 0; i < NST; ++i) {
        MBAR_WAIT(mbase + buf * 8, (ph >> buf) & 1);
        ph ^= (1u << buf);
        __syncthreads();
        if (i + NSTG - 1 < NST)
            issue(nbuf, i + NSTG - 1);

        const uint32_t sa = sbase + buf * STG;
        const uint32_t sb = sa + TSZ;
#pragma unroll
        for (int ks = 0; ks < 2; ++ks) {
            const uint32_t ko = ks * 32;
            uint32_t ah[4][4], al[4][4], bh[4][4], bl[4][4];
#pragma unroll
            for (int mi = 0; mi < 4; ++mi) {
                ldsm4(ah[mi], sa + a_rt[mi] + ((ko + a_koff) ^ a_sw[mi]));
                if (SPL)
                    ldsm4(al[mi], sa + a_rt[mi] + ((ko + a_koff + 64) ^ a_sw[mi]));
            }
            if (!SPL) {
                const int tt = i >> 1;
#pragma unroll
                for (int mi = 0; mi < 4; ++mi) {
                    const int r0 = warp_m * 64 + mi * 16 + (lane >> 2);
                    const __half2 a0 = __half2half2(s_alpha[tt * 128 + r0]);
                    const __half2 a1 = __half2half2(s_alpha[tt * 128 + r0 + 8]);
                    ah[mi][0] = mulh2(ah[mi][0], a0);
                    ah[mi][2] = mulh2(ah[mi][2], a0);
                    ah[mi][1] = mulh2(ah[mi][1], a1);
                    ah[mi][3] = mulh2(ah[mi][3], a1);
                }
            }
#pragma unroll
            for (int jp = 0; jp < 4; ++jp) {
                ldsm4(bh[jp], sb + b_rt[jp] + ((ko + b_koff) ^ b_sw[jp]));
                if (SPL)
                    ldsm4(bl[jp], sb + b_rt[jp] + ((ko + b_koff + 64) ^ b_sw[jp]));
            }
#pragma unroll
            for (int mi = 0; mi < 4; ++mi)
#pragma unroll
                for (int jp = 0; jp < 4; ++jp) {
                    mma16816(acc[mi][2*jp],   ah[mi], bh[jp]);
                    mma16816(acc[mi][2*jp+1], ah[mi], bh[jp] + 2);
                }
            if (SPL) {
#pragma unroll
                for (int mi = 0; mi < 4; ++mi)
#pragma unroll
                    for (int jp = 0; jp < 4; ++jp) {
                        mma16816(acc[mi][2*jp],   ah[mi], bl[jp]);
                        mma16816(acc[mi][2*jp+1], ah[mi], bl[jp] + 2);
                    }
#pragma unroll
                for (int mi = 0; mi < 4; ++mi)
#pragma unroll
                    for (int jp = 0; jp < 4; ++jp) {
                        mma16816(acc[mi][2*jp],   al[mi], bh[jp]);
                        mma16816(acc[mi][2*jp+1], al[mi], bh[jp] + 2);
                    }
            }
        }
        buf = (buf == NSTG - 1) ? 0 : buf + 1;
        nbuf = (nbuf == NSTG - 1) ? 0 : nbuf + 1;
    }

    // -----------------------------------------------------------------------
    // Epilogue
    // -----------------------------------------------------------------------
    const int rbase = bm + warp_m * 64 + (lane >> 2);
    const int cbase = bn + warp_n * 64 + (lane & 3) * 2;

    if (MODE == 1 || MODE == 2) {
        __half* st = (__half*)(smem + STG);   // MODE1 transpose staging
        if (MODE == 1) __syncthreads();
#pragma unroll
        for (int mi = 0; mi < 4; ++mi)
#pragma unroll
            for (int j = 0; j < 8; ++j) {
                const int gc = cbase + j * 8;
#pragma unroll
                for (int half = 0; half < 2; ++half) {
                    const int gr = rbase + mi * 16 + half * 8;
                    float v0 = acc[mi][j][half * 2 + 0];
                    float v1 = acc[mi][j][half * 2 + 1];
                    if (MODE == 1) {
                        const float2 bv = *(const float2*)(bias + gc);
                        v0 += bv.x; v1 += bv.y;
                    }
                    const __half h0 = __float2half(v0);
                    const __half h1 = __float2half(v1);
                    __half2 hp; hp.x = h0; hp.y = h1;
                    __half2 lp;
                    lp.x = __float2half(v0 - __half2float(h0));
                    lp.y = __float2half(v1 - __half2float(h1));
                    // tiled T3 write (Kdim = 512 -> 16 chunks)
                    const size_t tb = ((size_t)(gr >> 7) * 16 + (gc >> 5)) * 16384;
                    const uint32_t row = gr & 127, pat = (row & 7) << 4;
                    const uint32_t o = (gc & 31) * 2;
                    char* hb = outT3 + tb + row * 128;
                    *(__half2*)(hb + (o ^ pat)) = hp;
                    *(__half2*)(hb + ((64 + o) ^ pat)) = lp;
                    if (MODE == 1) {
                        st[(gc - bn)     * 136 + (gr - bm)] = h0;
                        st[(gc + 1 - bn) * 136 + (gr - bm)] = h1;
                    }
                }
            }
        if (MODE == 1) {
            __syncthreads();
            // tiled T1 hT write, fully coalesced (512B runs per warp)
            const int zb = bm >> 11, n0 = bm & 2047;
#pragma unroll
            for (int it = 0; it < 16; ++it) {
                const int f = it * 128 + tid;       // 0..2047
                const int c = f & 3, tr = f >> 2;   // tr = ch*128 + d_local
                const int dl = tr & 127, ch = tr >> 7;
                const int rdt = zb * DQ + bn + dl;
                const size_t tb = ((size_t)(rdt >> 7) * 64 + (n0 >> 5) + ch) * 8192;
                const uint32_t row = rdt & 127, pat = (row & 3) << 4;
                const float4 val = *(const float4*)(st + dl * 136 + ch * 32 + c * 8);
                *(float4*)(outT1 + tb + row * 64 + (((uint32_t)c * 16) ^ pat)) = val;
            }
        }
    } else if (MODE == 3) {
        const int tt = blockIdx.x * 2 + warp_n;   // global 64-tile index 0..31
#pragma unroll
        for (int mi = 0; mi < 4; ++mi)
#pragma unroll
            for (int j = 0; j < 8; ++j)
#pragma unroll
                for (int half = 0; half < 2; ++half) {
                    const int gr = rbase + mi * 16 + half * 8;
                    const int gc = cbase + j * 8;
                    const size_t o = (size_t)z * NQ * NQ + (size_t)gr * NQ + gc;
                    const int2 ad = *(const int2*)(adj + o);
                    if (!ad.x) acc[mi][j][half * 2]     = -1e30f;
                    if (!ad.y) acc[mi][j][half * 2 + 1] = -1e30f;
                }
#pragma unroll
        for (int mi = 0; mi < 4; ++mi)
#pragma unroll
            for (int half = 0; half < 2; ++half) {
                float m = -1e30f;
#pragma unroll
                for (int j = 0; j < 8; ++j)
                    m = fmaxf(m, fmaxf(acc[mi][j][half*2], acc[mi][j][half*2+1]));
                m = fmaxf(m, __shfl_xor_sync(0xffffffffu, m, 1));
                m = fmaxf(m, __shfl_xor_sync(0xffffffffu, m, 2));
                float ssum = 0.f;
#pragma unroll
                for (int j = 0; j < 8; ++j) {
                    const float e0 = __expf(acc[mi][j][half*2]     - m);
                    const float e1 = __expf(acc[mi][j][half*2 + 1] - m);
                    acc[mi][j][half*2]     = e0;
                    acc[mi][j][half*2 + 1] = e1;
                    ssum += e0 + e1;
                }
                ssum += __shfl_xor_sync(0xffffffffu, ssum, 1);
                ssum += __shfl_xor_sync(0xffffffffu, ssum, 2);
                if ((lane & 3) == 0) {
                    const int gr = rbase + mi * 16 + half * 8;
                    const size_t idx = (size_t)tt * MTOT + z * NQ + gr;
                    statm[idx] = m;
                    stats[idx] = ssum;
                }
            }
        // E write: tiled T1 (rows = z*NQ+gr, k = gc over NQ -> 64 chunks)
#pragma unroll
        for (int mi = 0; mi < 4; ++mi)
#pragma unroll
            for (int j = 0; j < 8; ++j)
#pragma unroll
                for (int half = 0; half < 2; ++half) {
                    const int gr = rbase + mi * 16 + half * 8;
                    const int gc = cbase + j * 8;
                    const size_t tb =
                        ((size_t)((z * NQ + gr) >> 7) * 64 + (gc >> 5)) * 8192;
                    const uint32_t row = gr & 127, pat = (row & 3) << 4;
                    const uint32_t o = (gc & 31) * 2;
                    *(__half2*)(outT1 + tb + row * 64 + (o ^ pat)) =
                        __floats2half2_rn(acc[mi][j][half*2], acc[mi][j][half*2+1]);
                }
    } else {
        // MODE 4: elu via fast exp
#pragma unroll
        for (int mi = 0; mi < 4; ++mi)
#pragma unroll
            for (int j = 0; j < 8; ++j) {
                const int gc = cbase + j * 8;
#pragma unroll
                for (int half = 0; half < 2; ++half) {
                    const int gr = rbase + mi * 16 + half * 8;
                    const float v0 = acc[mi][j][half * 2 + 0];
                    const float v1 = acc[mi][j][half * 2 + 1];
                    const size_t o = (size_t)z * NQ * DQ + (size_t)gr * DQ + gc;
                    float2 ov;
                    ov.x = (v0 > 0.f) ? v0 : (__expf(v0) - 1.f);
                    ov.y = (v1 > 0.f) ? v1 : (__expf(v1) - 1.f);
                    *(float2*)(outf + o) = ov;
                }
            }
    }
}

#define SMEM_G3P (3 * 32768 + 64)            // stages + mbars
#define SMEM_G4  (4 * 16384 + 8192 + 64)     // stages + alpha + mbars

// ---------------------------------------------------------------------------
// Merged split kernel: x (float4) + W + attn^T, all written TILED (T3).
// ---------------------------------------------------------------------------
__global__ __launch_bounds__(256) void k_split_all(
    const float4* __restrict__ x4, char* __restrict__ xt,
    const float* __restrict__ W, char* __restrict__ wt,
    const float* __restrict__ attn, char* __restrict__ att)
{
    const int gt = blockIdx.x * 256 + threadIdx.x;
    const int nthr = gridDim.x * 256;
    // x: MTOT*DQ/4 float4 elements (4 k's each, all within one 32-k chunk)
    for (int i = gt; i < MTOT * DQ / 4; i += nthr) {
        const int r = i >> 7;             // DQ/4 = 128 float4 per row
        const int k = (i & 127) * 4;
        const float4 v = x4[i];
        const __half2 h0 = __floats2half2_rn(v.x, v.y);
        const __half2 h1 = __floats2half2_rn(v.z, v.w);
        const float2 f0 = __half22float2(h0);
        const float2 f1 = __half22float2(h1);
        const __half2 l0 = __floats2half2_rn(v.x - f0.x, v.y - f0.y);
        const __half2 l1 = __floats2half2_rn(v.z - f1.x, v.w - f1.y);
        const size_t tb = ((size_t)(r >> 7) * 16 + (k >> 5)) * 16384;
        const uint32_t row = r & 127, pat = (row & 7) << 4;
        const uint32_t o = (k & 31) * 2;
        char* hb = xt + tb + row * 128;
        *(__half2*)(hb + ((o)      ^ pat)) = h0;
        *(__half2*)(hb + ((o + 4)  ^ pat)) = h1;
        *(__half2*)(hb + ((64 + o)     ^ pat)) = l0;
        *(__half2*)(hb + ((64 + o + 4) ^ pat)) = l1;
    }
    // W (rows = out dim) and attn^T (rows = 2nd index of attn): DQ*DQ each
    for (int i = gt; i < DQ * DQ; i += nthr) {
        const int r = i >> 9, k = i & 511;
        const size_t tb = ((size_t)(r >> 7) * 16 + (k >> 5)) * 16384;
        const uint32_t row = r & 127, pat = (row & 7) << 4;
        const uint32_t o = (k & 31) * 2;
        {
            const float v = W[i];
            const __half h = __float2half(v);
            char* hb = wt + tb + row * 128;
            *(__half*)(hb + (o ^ pat)) = h;
            *(__half*)(hb + ((64 + o) ^ pat)) = __float2half(v - __half2float(h));
        }
        {
            const float v = attn[(size_t)k * DQ + r];   // attn^T[r][k]
            const __half h = __float2half(v);
            char* hb = att + tb + row * 128;
            *(__half*)(hb + (o ^ pat)) = h;
            *(__half*)(hb + ((64 + o) ^ pat)) = __float2half(v - __half2float(h));
        }
    }
}

// ---------------------------------------------------------------------------
// Launch
// ---------------------------------------------------------------------------
extern "C" void kernel_launch(void* const* d_in, const int* in_sizes, int n_in,
                              void* d_out, int out_size)
{
    const float* x    = (const float*)d_in[0];
    const int*   adj  = (const int*)  d_in[1];
    const float* W    = (const float*)d_in[2];
    const float* bias = (const float*)d_in[3];
    const float* attn = (const float*)d_in[4];
    float* out = (float*)d_out;

    char *x_t, *w_t, *at_t, *h_t, *ha_t, *e_t, *ht_t;
    float *mt, *st;
    cudaGetSymbolAddress((void**)&x_t,  g_x_t);
    cudaGetSymbolAddress((void**)&w_t,  g_w_t);
    cudaGetSymbolAddress((void**)&at_t, g_at_t);
    cudaGetSymbolAddress((void**)&h_t,  g_h_t);
    cudaGetSymbolAddress((void**)&ha_t, g_ha_t);
    cudaGetSymbolAddress((void**)&e_t,  g_e_t);
    cudaGetSymbolAddress((void**)&ht_t, g_ht_t);
    cudaGetSymbolAddress((void**)&mt,   g_mt);
    cudaGetSymbolAddress((void**)&st,   g_st);

    cudaFuncSetAttribute(k_mma<1>, cudaFuncAttributeMaxDynamicSharedMemorySize, SMEM_G3P);
    cudaFuncSetAttribute(k_mma<2>, cudaFuncAttributeMaxDynamicSharedMemorySize, SMEM_G3P);
    cudaFuncSetAttribute(k_mma<3>, cudaFuncAttributeMaxDynamicSharedMemorySize, SMEM_G3P);
    cudaFuncSetAttribute(k_mma<4>, cudaFuncAttributeMaxDynamicSharedMemorySize, SMEM_G4);

    // Input splits -> tiled operands
    k_split_all<<<2048, 256>>>((const float4*)x, x_t, W, w_t, attn, at_t);

    // h = x @ W^T + b  (3-pass) -> h_t + ht_t
    k_mma<1><<<dim3(DQ / 128, MTOT / 128, 1), 128, SMEM_G3P>>>(
        x_t, w_t, bias, nullptr, nullptr, h_t, ht_t, nullptr, nullptr);

    // ha = h @ attn  (3-pass) -> ha_t
    k_mma<2><<<dim3(DQ / 128, MTOT / 128, 1), 128, SMEM_G3P>>>(
        h_t, at_t, nullptr, nullptr, nullptr, ha_t, nullptr, nullptr, nullptr);

    // scores -> masked exp tiles: e_t + (m_t, S_t)
    k_mma<3><<<dim3(NQ / 128, NQ / 128, BQ), 128, SMEM_G3P>>>(
        ha_t, h_t, nullptr, adj, nullptr, nullptr, e_t, mt, st);

    // out = elu( sum_t alpha_t E_t @ hT ) per batch
    k_mma<4><<<dim3(DQ / 128, NQ / 128, BQ), 128, SMEM_G4>>>(
        e_t, ht_t, nullptr, nullptr, out, nullptr, nullptr, mt, st);
}